// round 1
// baseline (speedup 1.0000x reference)
#include <cuda_runtime.h>
#include <math.h>

#define DM     1024
#define HEADS  16
#define DKH    64
#define BATCH  2
#define SEQ    2048
#define MROWS  (BATCH*SEQ)   // 4096

// Scratch (device globals: allocation-free per harness rules)
__device__ float g_q[HEADS*BATCH*SEQ*DKH];
__device__ float g_k[HEADS*BATCH*SEQ*DKH];
__device__ float g_v[HEADS*BATCH*SEQ*DKH];
__device__ float g_ctx[(size_t)MROWS*DM];

// ---------------------------------------------------------------------------
// GEMM: C[M,1024] = X[M,1024] @ W[1024,1024] + bias
// MODE 0: projection. blockIdx.z selects X in {query,key,value}; epilogue
//         scatters to head layout g_{q,k,v}[((h*B+b)*S+s)*64+d].
// MODE 1: output projection. X = g_ctx, plain row-major epilogue to Cout.
// 128x128 block tile, BK=16, 256 threads, 8x8 per-thread fragment.
// ---------------------------------------------------------------------------
template<int MODE>
__global__ __launch_bounds__(256, 2)
void gemm_kernel(const float* __restrict__ X0, const float* __restrict__ X1,
                 const float* __restrict__ X2,
                 const float* __restrict__ W, const float* __restrict__ bias,
                 float* __restrict__ Cout)
{
    __shared__ float As[16][128];   // A transposed: As[k][m]
    __shared__ float Bs[16][128];   // Bs[k][n]

    const int tid = threadIdx.x;
    const int z   = (MODE == 0) ? blockIdx.z : 0;
    const float* __restrict__ X =
        (MODE == 1) ? g_ctx : (z == 0 ? X0 : (z == 1 ? X1 : X2));

    const int gm0 = blockIdx.y * 128;
    const int gn0 = blockIdx.x * 128;
    const int ty = tid >> 4, tx = tid & 15;
    const int m0 = ty * 8, n0 = tx * 8;

    float acc[8][8];
#pragma unroll
    for (int i = 0; i < 8; i++)
#pragma unroll
        for (int j = 0; j < 8; j++) acc[i][j] = 0.f;

    for (int kt = 0; kt < DM; kt += 16) {
        float4 a4[2], b4[2];
#pragma unroll
        for (int l = 0; l < 2; l++) {
            int idx = tid + l * 256;
            int r = idx >> 2, k4 = idx & 3;              // A: 128 rows x 4 f4
            a4[l] = *(const float4*)&X[(size_t)(gm0 + r) * DM + kt + k4 * 4];
            int kb = idx >> 5, n4 = idx & 31;            // B: 16 rows x 32 f4
            b4[l] = *(const float4*)&W[(size_t)(kt + kb) * DM + gn0 + n4 * 4];
        }
        __syncthreads();
#pragma unroll
        for (int l = 0; l < 2; l++) {
            int idx = tid + l * 256;
            int r = idx >> 2, k4 = idx & 3;
            As[k4 * 4 + 0][r] = a4[l].x;
            As[k4 * 4 + 1][r] = a4[l].y;
            As[k4 * 4 + 2][r] = a4[l].z;
            As[k4 * 4 + 3][r] = a4[l].w;
            int kb = idx >> 5, n4 = idx & 31;
            *(float4*)&Bs[kb][n4 * 4] = b4[l];
        }
        __syncthreads();
#pragma unroll
        for (int k = 0; k < 16; k++) {
            float a[8], b[8];
            *(float4*)(a)     = *(float4*)&As[k][m0];
            *(float4*)(a + 4) = *(float4*)&As[k][m0 + 4];
            *(float4*)(b)     = *(float4*)&Bs[k][n0];
            *(float4*)(b + 4) = *(float4*)&Bs[k][n0 + 4];
#pragma unroll
            for (int i = 0; i < 8; i++)
#pragma unroll
                for (int j = 0; j < 8; j++) acc[i][j] += a[i] * b[j];
        }
    }

    float bv[8];
    *(float4*)(bv)     = *(const float4*)&bias[gn0 + n0];
    *(float4*)(bv + 4) = *(const float4*)&bias[gn0 + n0 + 4];

    if (MODE == 0) {
        float* out = (z == 0) ? g_q : (z == 1) ? g_k : g_v;
        const int gn = gn0 + n0;
        const int h = gn >> 6, d = gn & 63;   // 8 cols never cross a head edge
#pragma unroll
        for (int i = 0; i < 8; i++) {
            int gm = gm0 + m0 + i;
            int b = gm >> 11, s = gm & (SEQ - 1);
            float* p = &out[(((size_t)h * BATCH + b) * SEQ + s) * DKH + d];
            float4 v0 = {acc[i][0] + bv[0], acc[i][1] + bv[1],
                         acc[i][2] + bv[2], acc[i][3] + bv[3]};
            float4 v1 = {acc[i][4] + bv[4], acc[i][5] + bv[5],
                         acc[i][6] + bv[6], acc[i][7] + bv[7]};
            *(float4*)p = v0;
            *(float4*)(p + 4) = v1;
        }
    } else {
#pragma unroll
        for (int i = 0; i < 8; i++) {
            size_t gm = gm0 + m0 + i;
            float* p = &Cout[gm * DM + gn0 + n0];
            float4 v0 = {acc[i][0] + bv[0], acc[i][1] + bv[1],
                         acc[i][2] + bv[2], acc[i][3] + bv[3]};
            float4 v1 = {acc[i][4] + bv[4], acc[i][5] + bv[5],
                         acc[i][6] + bv[6], acc[i][7] + bv[7]};
            *(float4*)p = v0;
            *(float4*)(p + 4) = v1;
        }
    }
}

// ---------------------------------------------------------------------------
// Flash-style attention per (h,b): O = softmax(Q Kt / sqrt(S)) V
// BQ=128 query rows per block, streaming BKV=64 key/value rows per iter.
// Scores with the 1/sqrt(2048) scale are tiny (|s| <~ 0.6), so exp() without
// max-subtraction is numerically safe; row-sum kept as register partials,
// reduced via shfl at the end. 256 threads: 8 q-rows x 4 cols per thread.
// ---------------------------------------------------------------------------
#define ATT_SMEM_BYTES ((64*128 + 64*64 + 64*68 + 128*68) * 4)  // 101376

__global__ __launch_bounds__(256)
void attn_kernel()
{
    extern __shared__ float smf[];
    float* Qt = smf;                    // [64][128]  Qt[d][r], pre-scaled
    float* Kt = Qt + 64 * 128;          // [64][64]   Kt[d][c]
    float* Vs = Kt + 64 * 64;           // [64][68]   Vs[c][dv] (pad 4)
    float* Ps = Vs + 64 * 68;           // [128][68]  Ps[r][c]  (pad 4)

    const int tid = threadIdx.x;
    const int hb  = blockIdx.y;                 // h*BATCH + b
    const int q0  = blockIdx.x * 128;
    const float* __restrict__ Q = g_q + (size_t)hb * SEQ * DKH;
    const float* __restrict__ K = g_k + (size_t)hb * SEQ * DKH;
    const float* __restrict__ V = g_v + (size_t)hb * SEQ * DKH;

    const float inv_scale = rsqrtf((float)SEQ);

    // Load Q tile transposed into Qt[d][r], folding in the score scale.
#pragma unroll
    for (int l = 0; l < 8; l++) {
        int idx = tid + l * 256;        // float4 id 0..2047
        int r = idx & 127, d4 = idx >> 7;
        float4 v = *(const float4*)&Q[(size_t)(q0 + r) * DKH + d4 * 4];
        Qt[(d4 * 4 + 0) * 128 + r] = v.x * inv_scale;
        Qt[(d4 * 4 + 1) * 128 + r] = v.y * inv_scale;
        Qt[(d4 * 4 + 2) * 128 + r] = v.z * inv_scale;
        Qt[(d4 * 4 + 3) * 128 + r] = v.w * inv_scale;
    }

    const int ty = tid >> 4, tx = tid & 15;
    const int r0 = ty * 8, c0 = tx * 4;

    float4 acc[8];
    float  rsum[8];
#pragma unroll
    for (int i = 0; i < 8; i++) { acc[i] = make_float4(0.f,0.f,0.f,0.f); rsum[i] = 0.f; }

    for (int k0 = 0; k0 < SEQ; k0 += 64) {
        __syncthreads();   // previous O-phase done before overwriting Kt/Vs
        // Load K transposed + V direct
#pragma unroll
        for (int l = 0; l < 4; l++) {
            int idx = tid + l * 256;    // float4 id 0..1023
            int r = idx & 63, d4 = idx >> 6;
            float4 kv = *(const float4*)&K[(size_t)(k0 + r) * DKH + d4 * 4];
            Kt[(d4 * 4 + 0) * 64 + r] = kv.x;
            Kt[(d4 * 4 + 1) * 64 + r] = kv.y;
            Kt[(d4 * 4 + 2) * 64 + r] = kv.z;
            Kt[(d4 * 4 + 3) * 64 + r] = kv.w;
            int c = idx >> 4, dv4 = idx & 15;
            float4 vv = *(const float4*)&V[(size_t)(k0 + c) * DKH + dv4 * 4];
            *(float4*)&Vs[c * 68 + dv4 * 4] = vv;
        }
        __syncthreads();

        // S = (Q*scale) @ K^T  (8x4 fragment per thread)
        float s[8][4];
#pragma unroll
        for (int i = 0; i < 8; i++)
#pragma unroll
            for (int j = 0; j < 4; j++) s[i][j] = 0.f;

#pragma unroll 8
        for (int d = 0; d < 64; d++) {
            float qv[8], kv4[4];
            *(float4*)(qv)     = *(float4*)&Qt[d * 128 + r0];
            *(float4*)(qv + 4) = *(float4*)&Qt[d * 128 + r0 + 4];
            *(float4*)(kv4)    = *(float4*)&Kt[d * 64 + c0];
#pragma unroll
            for (int i = 0; i < 8; i++)
#pragma unroll
                for (int j = 0; j < 4; j++) s[i][j] += qv[i] * kv4[j];
        }

        // P = exp(S); accumulate row-sum partials; stage P for the PV GEMM
#pragma unroll
        for (int i = 0; i < 8; i++) {
            float4 p;
            p.x = __expf(s[i][0]); p.y = __expf(s[i][1]);
            p.z = __expf(s[i][2]); p.w = __expf(s[i][3]);
            rsum[i] += (p.x + p.y) + (p.z + p.w);
            *(float4*)&Ps[(r0 + i) * 68 + c0] = p;
        }
        __syncthreads();

        // O += P @ V  (thread owns rows r0..r0+7, dv cols c0..c0+3)
#pragma unroll 4
        for (int c4 = 0; c4 < 16; c4++) {
            float4 v0 = *(float4*)&Vs[(c4 * 4 + 0) * 68 + c0];
            float4 v1 = *(float4*)&Vs[(c4 * 4 + 1) * 68 + c0];
            float4 v2 = *(float4*)&Vs[(c4 * 4 + 2) * 68 + c0];
            float4 v3 = *(float4*)&Vs[(c4 * 4 + 3) * 68 + c0];
#pragma unroll
            for (int i = 0; i < 8; i++) {
                float4 pp = *(float4*)&Ps[(r0 + i) * 68 + c4 * 4];
                acc[i].x += pp.x * v0.x + pp.y * v1.x + pp.z * v2.x + pp.w * v3.x;
                acc[i].y += pp.x * v0.y + pp.y * v1.y + pp.z * v2.y + pp.w * v3.y;
                acc[i].z += pp.x * v0.z + pp.y * v1.z + pp.z * v2.z + pp.w * v3.z;
                acc[i].w += pp.x * v0.w + pp.y * v1.w + pp.z * v2.w + pp.w * v3.w;
            }
        }
    }

    // Row-sum reduction across the 16 lanes sharing each row block
#pragma unroll
    for (int i = 0; i < 8; i++) {
        float r = rsum[i];
        r += __shfl_xor_sync(0xffffffffu, r, 8);
        r += __shfl_xor_sync(0xffffffffu, r, 4);
        r += __shfl_xor_sync(0xffffffffu, r, 2);
        r += __shfl_xor_sync(0xffffffffu, r, 1);
        rsum[i] = 1.f / r;
    }

    // Write to concat layout: g_ctx[(b*S+s)*1024 + h*64 + dv]
    const int h = hb >> 1, b = hb & 1;
#pragma unroll
    for (int i = 0; i < 8; i++) {
        int srow = q0 + r0 + i;
        float4 o = acc[i];
        o.x *= rsum[i]; o.y *= rsum[i]; o.z *= rsum[i]; o.w *= rsum[i];
        *(float4*)&g_ctx[((size_t)(b * SEQ + srow)) * DM + h * DKH + c0] = o;
    }
}

// ---------------------------------------------------------------------------
extern "C" void kernel_launch(void* const* d_in, const int* in_sizes, int n_in,
                              void* d_out, int out_size)
{
    (void)in_sizes; (void)n_in; (void)out_size;
    const float* query = (const float*)d_in[0];
    const float* key   = (const float*)d_in[1];
    const float* value = (const float*)d_in[2];
    const float* Wq    = (const float*)d_in[3];
    const float* bq    = (const float*)d_in[4];
    const float* Wo    = (const float*)d_in[5];
    const float* bo    = (const float*)d_in[6];
    float* out = (float*)d_out;

    cudaFuncSetAttribute(attn_kernel,
                         cudaFuncAttributeMaxDynamicSharedMemorySize,
                         ATT_SMEM_BYTES);

    dim3 blk(256);
    // Fused q/k/v projection (all use Wq/bq — faithful to the reference bug)
    gemm_kernel<0><<<dim3(DM / 128, MROWS / 128, 3), blk>>>(
        query, key, value, Wq, bq, nullptr);
    // Attention per (h, b)
    attn_kernel<<<dim3(SEQ / 128, HEADS * BATCH), blk, ATT_SMEM_BYTES>>>();
    // Output projection
    gemm_kernel<1><<<dim3(DM / 128, MROWS / 128, 1), blk>>>(
        nullptr, nullptr, nullptr, Wo, bo, out);
}

// round 2
// speedup vs baseline: 1.5612x; 1.5612x over previous
#include <cuda_runtime.h>
#include <math.h>

#define DM     1024
#define HEADS  16
#define DKH    64
#define BATCH  2
#define SEQ    2048
#define MROWS  (BATCH*SEQ)   // 4096

typedef unsigned long long u64;

// Scratch (device globals: allocation-free per harness rules)
__device__ float g_q[HEADS*BATCH*SEQ*DKH];
__device__ float g_k[HEADS*BATCH*SEQ*DKH];
__device__ float g_v[HEADS*BATCH*SEQ*DKH];
__device__ float g_ctx[(size_t)MROWS*DM];

// ---- helpers --------------------------------------------------------------
__device__ __forceinline__ unsigned to_tf32(float f) {
    unsigned r;
    asm("cvt.rna.tf32.f32 %0, %1;" : "=r"(r) : "f"(f));
    return r;
}
__device__ __forceinline__ u64 pk2(float lo, float hi) {
    u64 r;
    asm("mov.b64 %0, {%1, %2};" : "=l"(r) : "f"(lo), "f"(hi));
    return r;
}
__device__ __forceinline__ void unpk2(float &lo, float &hi, u64 v) {
    asm("mov.b64 {%0, %1}, %2;" : "=f"(lo), "=f"(hi) : "l"(v));
}
__device__ __forceinline__ void fma2(u64 &d, u64 a, u64 b) {
    asm("fma.rn.f32x2 %0, %1, %2, %0;" : "+l"(d) : "l"(a), "l"(b));
}
__device__ __forceinline__ void mma_tf32(float d[4], const unsigned a[4],
                                         const unsigned b[2]) {
    asm("mma.sync.aligned.m16n8k8.row.col.f32.tf32.tf32.f32 "
        "{%0,%1,%2,%3}, {%4,%5,%6,%7}, {%8,%9}, {%0,%1,%2,%3};"
        : "+f"(d[0]), "+f"(d[1]), "+f"(d[2]), "+f"(d[3])
        : "r"(a[0]), "r"(a[1]), "r"(a[2]), "r"(a[3]), "r"(b[0]), "r"(b[1]));
}

// ---------------------------------------------------------------------------
// TF32 tensor-core GEMM: C[M,1024] = X[M,1024] @ W[1024,1024] + bias
// MODE 0: q/k/v projection (z selects X, epilogue scatters to head layout)
// MODE 1: output projection from g_ctx
// 128x128 block tile, BK=16, 256 threads = 8 warps (2M x 4N), warp tile 64x32.
// Smem strides chosen conflict-free for the mma fragment LDS patterns:
//   As[m][20]:  a-frag bank = (20*grp + qi) % 32  -> 32 distinct
//   Bs[k][136]: b-frag bank = (8*qi + grp)  % 32  -> 32 distinct
// ---------------------------------------------------------------------------
template<int MODE>
__global__ __launch_bounds__(256)
void gemm_kernel(const float* __restrict__ X0, const float* __restrict__ X1,
                 const float* __restrict__ X2,
                 const float* __restrict__ W, const float* __restrict__ bias,
                 float* __restrict__ Cout)
{
    __shared__ unsigned As[128 * 20];
    __shared__ unsigned Bs[16 * 136];

    const int tid  = threadIdx.x;
    const int warp = tid >> 5, lane = tid & 31;
    const int wm = warp >> 2, wn = warp & 3;      // 2 x 4 warp grid
    const int grp = lane >> 2, qi = lane & 3;

    const int z = (MODE == 0) ? blockIdx.z : 0;
    const float* __restrict__ X =
        (MODE == 1) ? g_ctx : (z == 0 ? X0 : (z == 1 ? X1 : X2));

    const int gm0 = blockIdx.y * 128;
    const int gn0 = blockIdx.x * 128;

    float d[4][4][4];
#pragma unroll
    for (int mi = 0; mi < 4; mi++)
#pragma unroll
        for (int ni = 0; ni < 4; ni++)
#pragma unroll
            for (int r = 0; r < 4; r++) d[mi][ni][r] = 0.f;

    for (int kt = 0; kt < DM; kt += 16) {
        float4 a4[2], b4[2];
#pragma unroll
        for (int l = 0; l < 2; l++) {
            int idx = tid + l * 256;
            int r = idx >> 2, k4 = idx & 3;              // A: 128 rows x 4 f4
            a4[l] = *(const float4*)&X[(size_t)(gm0 + r) * DM + kt + k4 * 4];
            int kb = idx >> 5, n4 = idx & 31;            // B: 16 rows x 32 f4
            b4[l] = *(const float4*)&W[(size_t)(kt + kb) * DM + gn0 + n4 * 4];
        }
        __syncthreads();
#pragma unroll
        for (int l = 0; l < 2; l++) {
            int idx = tid + l * 256;
            int r = idx >> 2, k4 = idx & 3;
            unsigned* ap = &As[r * 20 + k4 * 4];
            ap[0] = to_tf32(a4[l].x); ap[1] = to_tf32(a4[l].y);
            ap[2] = to_tf32(a4[l].z); ap[3] = to_tf32(a4[l].w);
            int kb = idx >> 5, n4 = idx & 31;
            unsigned* bp = &Bs[kb * 136 + n4 * 4];
            bp[0] = to_tf32(b4[l].x); bp[1] = to_tf32(b4[l].y);
            bp[2] = to_tf32(b4[l].z); bp[3] = to_tf32(b4[l].w);
        }
        __syncthreads();

#pragma unroll
        for (int k8 = 0; k8 < 16; k8 += 8) {
            unsigned af[4][4], bf[4][2];
#pragma unroll
            for (int mi = 0; mi < 4; mi++) {
                int row = wm * 64 + mi * 16 + grp;
                const unsigned* p = &As[row * 20 + k8 + qi];
                af[mi][0] = p[0];
                af[mi][1] = p[8 * 20];
                af[mi][2] = p[4];
                af[mi][3] = p[8 * 20 + 4];
            }
#pragma unroll
            for (int ni = 0; ni < 4; ni++) {
                int col = wn * 32 + ni * 8 + grp;
                bf[ni][0] = Bs[(k8 + qi) * 136 + col];
                bf[ni][1] = Bs[(k8 + qi + 4) * 136 + col];
            }
#pragma unroll
            for (int mi = 0; mi < 4; mi++)
#pragma unroll
                for (int ni = 0; ni < 4; ni++)
                    mma_tf32(d[mi][ni], af[mi], bf[ni]);
        }
    }

    // Epilogue: thread owns cols gcol,gcol+1 at rows gr and gr+8 per tile.
#pragma unroll
    for (int ni = 0; ni < 4; ni++) {
        int gcol = gn0 + wn * 32 + ni * 8 + qi * 2;
        float b0 = bias[gcol], b1 = bias[gcol + 1];
#pragma unroll
        for (int mi = 0; mi < 4; mi++) {
            int gr = gm0 + wm * 64 + mi * 16 + grp;
#pragma unroll
            for (int half = 0; half < 2; half++) {
                int gm = gr + half * 8;
                float v0 = d[mi][ni][half * 2 + 0] + b0;
                float v1 = d[mi][ni][half * 2 + 1] + b1;
                if (MODE == 0) {
                    float* out = (z == 0) ? g_q : (z == 1) ? g_k : g_v;
                    int h = gcol >> 6, dd = gcol & 63;
                    int b = gm >> 11, s = gm & (SEQ - 1);
                    float* p = &out[(((size_t)h * BATCH + b) * SEQ + s) * DKH + dd];
                    *(float2*)p = make_float2(v0, v1);
                } else {
                    float* p = &Cout[(size_t)gm * DM + gcol];
                    *(float2*)p = make_float2(v0, v1);
                }
            }
        }
    }
}

// ---------------------------------------------------------------------------
// Flash-style attention per (h,b): O = softmax(Q Kt / sqrt(S)) V
// Inner GEMM loops use packed fma.rn.f32x2 (FFMA2) for 2x fp32 rate.
// ---------------------------------------------------------------------------
#define ATT_SMEM_BYTES ((64*128 + 64*64 + 64*68 + 128*68) * 4)  // 101376

__global__ __launch_bounds__(256)
void attn_kernel()
{
    extern __shared__ float smf[];
    float* Qt = smf;                    // [64][128]  Qt[d][r], pre-scaled
    float* Kt = Qt + 64 * 128;          // [64][64]   Kt[d][c]
    float* Vs = Kt + 64 * 64;           // [64][68]   Vs[c][dv] (pad 4)
    float* Ps = Vs + 64 * 68;           // [128][68]  Ps[r][c]  (pad 4)

    const int tid = threadIdx.x;
    const int hb  = blockIdx.y;                 // h*BATCH + b
    const int q0  = blockIdx.x * 128;
    const float* __restrict__ Q = g_q + (size_t)hb * SEQ * DKH;
    const float* __restrict__ K = g_k + (size_t)hb * SEQ * DKH;
    const float* __restrict__ V = g_v + (size_t)hb * SEQ * DKH;

    const float inv_scale = rsqrtf((float)SEQ);

#pragma unroll
    for (int l = 0; l < 8; l++) {
        int idx = tid + l * 256;        // float4 id 0..2047
        int r = idx & 127, d4 = idx >> 7;
        float4 v = *(const float4*)&Q[(size_t)(q0 + r) * DKH + d4 * 4];
        Qt[(d4 * 4 + 0) * 128 + r] = v.x * inv_scale;
        Qt[(d4 * 4 + 1) * 128 + r] = v.y * inv_scale;
        Qt[(d4 * 4 + 2) * 128 + r] = v.z * inv_scale;
        Qt[(d4 * 4 + 3) * 128 + r] = v.w * inv_scale;
    }

    const int ty = tid >> 4, tx = tid & 15;
    const int r0 = ty * 8, c0 = tx * 4;

    u64   acc2[8][2];        // packed O accumulators: rows r0..r0+7, dv c0..c0+3
    float rsum[8];
#pragma unroll
    for (int i = 0; i < 8; i++) {
        acc2[i][0] = 0ull; acc2[i][1] = 0ull; rsum[i] = 0.f;
    }

    for (int k0 = 0; k0 < SEQ; k0 += 64) {
        __syncthreads();
#pragma unroll
        for (int l = 0; l < 4; l++) {
            int idx = tid + l * 256;
            int r = idx & 63, d4 = idx >> 6;
            float4 kv = *(const float4*)&K[(size_t)(k0 + r) * DKH + d4 * 4];
            Kt[(d4 * 4 + 0) * 64 + r] = kv.x;
            Kt[(d4 * 4 + 1) * 64 + r] = kv.y;
            Kt[(d4 * 4 + 2) * 64 + r] = kv.z;
            Kt[(d4 * 4 + 3) * 64 + r] = kv.w;
            int c = idx >> 4, dv4 = idx & 15;
            float4 vv = *(const float4*)&V[(size_t)(k0 + c) * DKH + dv4 * 4];
            *(float4*)&Vs[c * 68 + dv4 * 4] = vv;
        }
        __syncthreads();

        // S = (Q*scale) @ K^T, packed over the 4 key columns (2 x f32x2)
        u64 s2[8][2];
#pragma unroll
        for (int i = 0; i < 8; i++) { s2[i][0] = 0ull; s2[i][1] = 0ull; }

#pragma unroll 8
        for (int dd = 0; dd < 64; dd++) {
            float qv[8];
            *(float4*)(qv)     = *(float4*)&Qt[dd * 128 + r0];
            *(float4*)(qv + 4) = *(float4*)&Qt[dd * 128 + r0 + 4];
            const u64* kp = (const u64*)&Kt[dd * 64 + c0];
            u64 kv0 = kp[0], kv1 = kp[1];
#pragma unroll
            for (int i = 0; i < 8; i++) {
                u64 qd = pk2(qv[i], qv[i]);
                fma2(s2[i][0], qd, kv0);
                fma2(s2[i][1], qd, kv1);
            }
        }

        // P = exp(S); row-sum partials; stage P
#pragma unroll
        for (int i = 0; i < 8; i++) {
            float sa, sb, sc, sd;
            unpk2(sa, sb, s2[i][0]);
            unpk2(sc, sd, s2[i][1]);
            float4 p;
            p.x = __expf(sa); p.y = __expf(sb);
            p.z = __expf(sc); p.w = __expf(sd);
            rsum[i] += (p.x + p.y) + (p.z + p.w);
            *(float4*)&Ps[(r0 + i) * 68 + c0] = p;
        }
        __syncthreads();

        // O += P @ V, packed over dv (2 x f32x2 per row)
#pragma unroll 4
        for (int c4 = 0; c4 < 16; c4++) {
            u64 vv[4][2];
#pragma unroll
            for (int c = 0; c < 4; c++) {
                const u64* vp = (const u64*)&Vs[(c4 * 4 + c) * 68 + c0];
                vv[c][0] = vp[0]; vv[c][1] = vp[1];
            }
#pragma unroll
            for (int i = 0; i < 8; i++) {
                float4 pp = *(float4*)&Ps[(r0 + i) * 68 + c4 * 4];
                u64 px = pk2(pp.x, pp.x), py = pk2(pp.y, pp.y);
                u64 pz = pk2(pp.z, pp.z), pw = pk2(pp.w, pp.w);
                fma2(acc2[i][0], px, vv[0][0]); fma2(acc2[i][1], px, vv[0][1]);
                fma2(acc2[i][0], py, vv[1][0]); fma2(acc2[i][1], py, vv[1][1]);
                fma2(acc2[i][0], pz, vv[2][0]); fma2(acc2[i][1], pz, vv[2][1]);
                fma2(acc2[i][0], pw, vv[3][0]); fma2(acc2[i][1], pw, vv[3][1]);
            }
        }
    }

#pragma unroll
    for (int i = 0; i < 8; i++) {
        float r = rsum[i];
        r += __shfl_xor_sync(0xffffffffu, r, 8);
        r += __shfl_xor_sync(0xffffffffu, r, 4);
        r += __shfl_xor_sync(0xffffffffu, r, 2);
        r += __shfl_xor_sync(0xffffffffu, r, 1);
        rsum[i] = 1.f / r;
    }

    const int h = hb >> 1, b = hb & 1;
#pragma unroll
    for (int i = 0; i < 8; i++) {
        int srow = q0 + r0 + i;
        float4 o;
        unpk2(o.x, o.y, acc2[i][0]);
        unpk2(o.z, o.w, acc2[i][1]);
        o.x *= rsum[i]; o.y *= rsum[i]; o.z *= rsum[i]; o.w *= rsum[i];
        *(float4*)&g_ctx[((size_t)(b * SEQ + srow)) * DM + h * DKH + c0] = o;
    }
}

// ---------------------------------------------------------------------------
extern "C" void kernel_launch(void* const* d_in, const int* in_sizes, int n_in,
                              void* d_out, int out_size)
{
    (void)in_sizes; (void)n_in; (void)out_size;
    const float* query = (const float*)d_in[0];
    const float* key   = (const float*)d_in[1];
    const float* value = (const float*)d_in[2];
    const float* Wq    = (const float*)d_in[3];
    const float* bq    = (const float*)d_in[4];
    const float* Wo    = (const float*)d_in[5];
    const float* bo    = (const float*)d_in[6];
    float* out = (float*)d_out;

    cudaFuncSetAttribute(attn_kernel,
                         cudaFuncAttributeMaxDynamicSharedMemorySize,
                         ATT_SMEM_BYTES);

    dim3 blk(256);
    gemm_kernel<0><<<dim3(DM / 128, MROWS / 128, 3), blk>>>(
        query, key, value, Wq, bq, nullptr);
    attn_kernel<<<dim3(SEQ / 128, HEADS * BATCH), blk, ATT_SMEM_BYTES>>>();
    gemm_kernel<1><<<dim3(DM / 128, MROWS / 128, 1), blk>>>(
        nullptr, nullptr, nullptr, Wo, bo, out);
}

// round 3
// speedup vs baseline: 2.6185x; 1.6772x over previous
#include <cuda_runtime.h>
#include <math.h>

#define DM     1024
#define HEADS  16
#define DKH    64
#define BATCH  2
#define SEQ    2048
#define MROWS  (BATCH*SEQ)   // 4096

// Scratch (device globals: allocation-free per harness rules)
__device__ float g_q[HEADS*BATCH*SEQ*DKH];
__device__ float g_k[HEADS*BATCH*SEQ*DKH];
__device__ float g_v[HEADS*BATCH*SEQ*DKH];
__device__ float g_ctx[(size_t)MROWS*DM];

// ---- helpers --------------------------------------------------------------
__device__ __forceinline__ unsigned to_tf32(float f) {
    unsigned r;
    asm("cvt.rna.tf32.f32 %0, %1;" : "=r"(r) : "f"(f));
    return r;
}
__device__ __forceinline__ void mma_tf32(float d[4], const unsigned a[4],
                                         const unsigned b[2]) {
    asm("mma.sync.aligned.m16n8k8.row.col.f32.tf32.tf32.f32 "
        "{%0,%1,%2,%3}, {%4,%5,%6,%7}, {%8,%9}, {%0,%1,%2,%3};"
        : "+f"(d[0]), "+f"(d[1]), "+f"(d[2]), "+f"(d[3])
        : "r"(a[0]), "r"(a[1]), "r"(a[2]), "r"(a[3]), "r"(b[0]), "r"(b[1]));
}

// ---------------------------------------------------------------------------
// TF32 tensor-core GEMM: C[M,1024] = X[M,1024] @ W[1024,1024] + bias
// MODE 0: q/k/v projection (z selects X, epilogue scatters to head layout)
// MODE 1: output projection from g_ctx
// ---------------------------------------------------------------------------
template<int MODE>
__global__ __launch_bounds__(256)
void gemm_kernel(const float* __restrict__ X0, const float* __restrict__ X1,
                 const float* __restrict__ X2,
                 const float* __restrict__ W, const float* __restrict__ bias,
                 float* __restrict__ Cout)
{
    __shared__ unsigned As[128 * 20];
    __shared__ unsigned Bs[16 * 136];

    const int tid  = threadIdx.x;
    const int warp = tid >> 5, lane = tid & 31;
    const int wm = warp >> 2, wn = warp & 3;      // 2 x 4 warp grid
    const int grp = lane >> 2, qi = lane & 3;

    const int z = (MODE == 0) ? blockIdx.z : 0;
    const float* __restrict__ X =
        (MODE == 1) ? g_ctx : (z == 0 ? X0 : (z == 1 ? X1 : X2));

    const int gm0 = blockIdx.y * 128;
    const int gn0 = blockIdx.x * 128;

    float d[4][4][4];
#pragma unroll
    for (int mi = 0; mi < 4; mi++)
#pragma unroll
        for (int ni = 0; ni < 4; ni++)
#pragma unroll
            for (int r = 0; r < 4; r++) d[mi][ni][r] = 0.f;

    for (int kt = 0; kt < DM; kt += 16) {
        float4 a4[2], b4[2];
#pragma unroll
        for (int l = 0; l < 2; l++) {
            int idx = tid + l * 256;
            int r = idx >> 2, k4 = idx & 3;              // A: 128 rows x 4 f4
            a4[l] = *(const float4*)&X[(size_t)(gm0 + r) * DM + kt + k4 * 4];
            int kb = idx >> 5, n4 = idx & 31;            // B: 16 rows x 32 f4
            b4[l] = *(const float4*)&W[(size_t)(kt + kb) * DM + gn0 + n4 * 4];
        }
        __syncthreads();
#pragma unroll
        for (int l = 0; l < 2; l++) {
            int idx = tid + l * 256;
            int r = idx >> 2, k4 = idx & 3;
            unsigned* ap = &As[r * 20 + k4 * 4];
            ap[0] = to_tf32(a4[l].x); ap[1] = to_tf32(a4[l].y);
            ap[2] = to_tf32(a4[l].z); ap[3] = to_tf32(a4[l].w);
            int kb = idx >> 5, n4 = idx & 31;
            unsigned* bp = &Bs[kb * 136 + n4 * 4];
            bp[0] = to_tf32(b4[l].x); bp[1] = to_tf32(b4[l].y);
            bp[2] = to_tf32(b4[l].z); bp[3] = to_tf32(b4[l].w);
        }
        __syncthreads();

#pragma unroll
        for (int k8 = 0; k8 < 16; k8 += 8) {
            unsigned af[4][4], bf[4][2];
#pragma unroll
            for (int mi = 0; mi < 4; mi++) {
                int row = wm * 64 + mi * 16 + grp;
                const unsigned* p = &As[row * 20 + k8 + qi];
                af[mi][0] = p[0];
                af[mi][1] = p[8 * 20];
                af[mi][2] = p[4];
                af[mi][3] = p[8 * 20 + 4];
            }
#pragma unroll
            for (int ni = 0; ni < 4; ni++) {
                int col = wn * 32 + ni * 8 + grp;
                bf[ni][0] = Bs[(k8 + qi) * 136 + col];
                bf[ni][1] = Bs[(k8 + qi + 4) * 136 + col];
            }
#pragma unroll
            for (int mi = 0; mi < 4; mi++)
#pragma unroll
                for (int ni = 0; ni < 4; ni++)
                    mma_tf32(d[mi][ni], af[mi], bf[ni]);
        }
    }

#pragma unroll
    for (int ni = 0; ni < 4; ni++) {
        int gcol = gn0 + wn * 32 + ni * 8 + qi * 2;
        float b0 = bias[gcol], b1 = bias[gcol + 1];
#pragma unroll
        for (int mi = 0; mi < 4; mi++) {
            int gr = gm0 + wm * 64 + mi * 16 + grp;
#pragma unroll
            for (int half = 0; half < 2; half++) {
                int gm = gr + half * 8;
                float v0 = d[mi][ni][half * 2 + 0] + b0;
                float v1 = d[mi][ni][half * 2 + 1] + b1;
                if (MODE == 0) {
                    float* out = (z == 0) ? g_q : (z == 1) ? g_k : g_v;
                    int h = gcol >> 6, dd = gcol & 63;
                    int b = gm >> 11, s = gm & (SEQ - 1);
                    float* p = &out[(((size_t)h * BATCH + b) * SEQ + s) * DKH + dd];
                    *(float2*)p = make_float2(v0, v1);
                } else {
                    float* p = &Cout[(size_t)gm * DM + gcol];
                    *(float2*)p = make_float2(v0, v1);
                }
            }
        }
    }
}

// ---------------------------------------------------------------------------
// TF32 tensor-core flash attention per (h,b): O = softmax(Q Kt / sqrt(S)) V
// 256 threads = 8 warps; warp w owns q-rows [w*16, w*16+16) of a 128-row tile.
// Per 64-kv iter: S = QKt via mma (accs in regs), P = exp(S) -> tf32 to
// warp-private smem rows, O += P V via mma. Rowsums are per-lane partials,
// reduced by shfl at the end (scores are tiny: no max-subtraction needed).
// All smem strides 68 -> conflict-free mma fragment LDS.
// ---------------------------------------------------------------------------
#define AT_STR 68
#define ATT_SMEM_BYTES ((128 + 64 + 64 + 128) * AT_STR * 4)   // 104448

__global__ __launch_bounds__(256)
void attn_kernel()
{
    extern __shared__ unsigned smu[];
    unsigned* Qs = smu;                       // [128][68] tf32, pre-scaled
    unsigned* Ks = Qs + 128 * AT_STR;         // [64][68]  tf32
    unsigned* Vs = Ks + 64 * AT_STR;          // [64][68]  tf32
    unsigned* Ps = Vs + 64 * AT_STR;          // [128][68] tf32

    const int tid  = threadIdx.x;
    const int warp = tid >> 5, lane = tid & 31;
    const int grp  = lane >> 2, qi = lane & 3;
    const int hb   = blockIdx.y;
    const int q0   = blockIdx.x * 128;

    const float* __restrict__ Q = g_q + (size_t)hb * SEQ * DKH;
    const float* __restrict__ K = g_k + (size_t)hb * SEQ * DKH;
    const float* __restrict__ V = g_v + (size_t)hb * SEQ * DKH;

    const float inv_scale = rsqrtf((float)SEQ);

    // Stage Q (scale folded in): 128x64 = 2048 float4, 8 per thread
#pragma unroll
    for (int l = 0; l < 8; l++) {
        int idx = tid + l * 256;
        int r = idx >> 4, c4 = idx & 15;
        float4 v = *(const float4*)&Q[(size_t)(q0 + r) * DKH + c4 * 4];
        uint4 t;
        t.x = to_tf32(v.x * inv_scale); t.y = to_tf32(v.y * inv_scale);
        t.z = to_tf32(v.z * inv_scale); t.w = to_tf32(v.w * inv_scale);
        *(uint4*)&Qs[r * AT_STR + c4 * 4] = t;
    }

    const int row0 = warp * 16;

    float o[8][4];         // persistent O accs: rows {grp, grp+8}, 8 n-tiles
    float rsum0 = 0.f, rsum1 = 0.f;
#pragma unroll
    for (int ni = 0; ni < 8; ni++)
#pragma unroll
        for (int r = 0; r < 4; r++) o[ni][r] = 0.f;

    for (int k0 = 0; k0 < SEQ; k0 += 64) {
        __syncthreads();    // prev iter's Ks/Vs reads done
        // Stage K, V tiles: 64x64 each = 1024 f4, 4 per thread per tensor
#pragma unroll
        for (int l = 0; l < 4; l++) {
            int idx = tid + l * 256;
            int r = idx >> 4, c4 = idx & 15;
            float4 kv = *(const float4*)&K[(size_t)(k0 + r) * DKH + c4 * 4];
            uint4 tk;
            tk.x = to_tf32(kv.x); tk.y = to_tf32(kv.y);
            tk.z = to_tf32(kv.z); tk.w = to_tf32(kv.w);
            *(uint4*)&Ks[r * AT_STR + c4 * 4] = tk;
            float4 vv = *(const float4*)&V[(size_t)(k0 + r) * DKH + c4 * 4];
            uint4 tv;
            tv.x = to_tf32(vv.x); tv.y = to_tf32(vv.y);
            tv.z = to_tf32(vv.z); tv.w = to_tf32(vv.w);
            *(uint4*)&Vs[r * AT_STR + c4 * 4] = tv;
        }
        __syncthreads();

        // ---- S = (Q*scale) @ K^T : warp rows [row0,row0+16) x kv cols [0,64)
        float s[8][4];
#pragma unroll
        for (int ni = 0; ni < 8; ni++)
#pragma unroll
            for (int r = 0; r < 4; r++) s[ni][r] = 0.f;

#pragma unroll
        for (int k8 = 0; k8 < 64; k8 += 8) {
            unsigned a[4];
            const unsigned* ap = &Qs[(row0 + grp) * AT_STR + k8 + qi];
            a[0] = ap[0];
            a[1] = ap[8 * AT_STR];
            a[2] = ap[4];
            a[3] = ap[8 * AT_STR + 4];
#pragma unroll
            for (int ni = 0; ni < 8; ni++) {
                unsigned b[2];
                const unsigned* bp = &Ks[(ni * 8 + grp) * AT_STR + k8 + qi];
                b[0] = bp[0];
                b[1] = bp[4];
                mma_tf32(s[ni], a, b);
            }
        }

        // ---- P = exp(S), rowsum partials, store tf32 P to warp-private rows
#pragma unroll
        for (int ni = 0; ni < 8; ni++) {
            float e0 = __expf(s[ni][0]), e1 = __expf(s[ni][1]);
            float e2 = __expf(s[ni][2]), e3 = __expf(s[ni][3]);
            rsum0 += e0 + e1;
            rsum1 += e2 + e3;
            uint2 p0 = make_uint2(to_tf32(e0), to_tf32(e1));
            uint2 p1 = make_uint2(to_tf32(e2), to_tf32(e3));
            *(uint2*)&Ps[(row0 + grp) * AT_STR + ni * 8 + qi * 2]     = p0;
            *(uint2*)&Ps[(row0 + 8 + grp) * AT_STR + ni * 8 + qi * 2] = p1;
        }
        __syncwarp();   // P rows are warp-private; warp-level sync suffices

        // ---- O += P @ V : A = P rows [row0,row0+16), B = V [64 kv][64 dv]
#pragma unroll
        for (int k8 = 0; k8 < 64; k8 += 8) {
            unsigned a[4];
            const unsigned* ap = &Ps[(row0 + grp) * AT_STR + k8 + qi];
            a[0] = ap[0];
            a[1] = ap[8 * AT_STR];
            a[2] = ap[4];
            a[3] = ap[8 * AT_STR + 4];
#pragma unroll
            for (int ni = 0; ni < 8; ni++) {
                unsigned b[2];
                const unsigned* bp = &Vs[(k8 + qi) * AT_STR + ni * 8 + grp];
                b[0] = bp[0];
                b[1] = bp[4 * AT_STR];
                mma_tf32(o[ni], a, b);
            }
        }
    }

    // Reduce rowsums across the 4 qi lanes of each quad-row
    rsum0 += __shfl_xor_sync(0xffffffffu, rsum0, 1);
    rsum0 += __shfl_xor_sync(0xffffffffu, rsum0, 2);
    rsum1 += __shfl_xor_sync(0xffffffffu, rsum1, 1);
    rsum1 += __shfl_xor_sync(0xffffffffu, rsum1, 2);
    const float rinv0 = 1.f / rsum0;
    const float rinv1 = 1.f / rsum1;

    // Write to concat layout g_ctx[(b*S+s)*1024 + h*64 + dv]
    const int h = hb >> 1, b = hb & 1;
    const int sr0 = q0 + row0 + grp;
#pragma unroll
    for (int ni = 0; ni < 8; ni++) {
        int col = h * DKH + ni * 8 + qi * 2;
        *(float2*)&g_ctx[((size_t)(b * SEQ + sr0)) * DM + col] =
            make_float2(o[ni][0] * rinv0, o[ni][1] * rinv0);
        *(float2*)&g_ctx[((size_t)(b * SEQ + sr0 + 8)) * DM + col] =
            make_float2(o[ni][2] * rinv1, o[ni][3] * rinv1);
    }
}

// ---------------------------------------------------------------------------
extern "C" void kernel_launch(void* const* d_in, const int* in_sizes, int n_in,
                              void* d_out, int out_size)
{
    (void)in_sizes; (void)n_in; (void)out_size;
    const float* query = (const float*)d_in[0];
    const float* key   = (const float*)d_in[1];
    const float* value = (const float*)d_in[2];
    const float* Wq    = (const float*)d_in[3];
    const float* bq    = (const float*)d_in[4];
    const float* Wo    = (const float*)d_in[5];
    const float* bo    = (const float*)d_in[6];
    float* out = (float*)d_out;

    cudaFuncSetAttribute(attn_kernel,
                         cudaFuncAttributeMaxDynamicSharedMemorySize,
                         ATT_SMEM_BYTES);

    dim3 blk(256);
    gemm_kernel<0><<<dim3(DM / 128, MROWS / 128, 3), blk>>>(
        query, key, value, Wq, bq, nullptr);
    attn_kernel<<<dim3(SEQ / 128, HEADS * BATCH), blk, ATT_SMEM_BYTES>>>();
    gemm_kernel<1><<<dim3(DM / 128, MROWS / 128, 1), blk>>>(
        nullptr, nullptr, nullptr, Wo, bo, out);
}

// round 4
// speedup vs baseline: 2.8093x; 1.0729x over previous
#include <cuda_runtime.h>
#include <math.h>

#define DM     1024
#define HEADS  16
#define DKH    64
#define BATCH  2
#define SEQ    2048
#define MROWS  (BATCH*SEQ)   // 4096

// Scratch (device globals: allocation-free per harness rules)
__device__ float g_q[HEADS*BATCH*SEQ*DKH];
__device__ float g_k[HEADS*BATCH*SEQ*DKH];
__device__ float g_v[HEADS*BATCH*SEQ*DKH];
__device__ float g_ctx[(size_t)MROWS*DM];

// ---- helpers --------------------------------------------------------------
__device__ __forceinline__ unsigned to_tf32(float f) {
    unsigned r;
    asm("cvt.rna.tf32.f32 %0, %1;" : "=r"(r) : "f"(f));
    return r;
}
__device__ __forceinline__ uint4 cvt4(float4 v) {
    uint4 t;
    t.x = to_tf32(v.x); t.y = to_tf32(v.y);
    t.z = to_tf32(v.z); t.w = to_tf32(v.w);
    return t;
}
__device__ __forceinline__ void mma_tf32(float d[4], const unsigned a[4],
                                         const unsigned b[2]) {
    asm("mma.sync.aligned.m16n8k8.row.col.f32.tf32.tf32.f32 "
        "{%0,%1,%2,%3}, {%4,%5,%6,%7}, {%8,%9}, {%0,%1,%2,%3};"
        : "+f"(d[0]), "+f"(d[1]), "+f"(d[2]), "+f"(d[3])
        : "r"(a[0]), "r"(a[1]), "r"(a[2]), "r"(a[3]), "r"(b[0]), "r"(b[1]));
}

// ---------------------------------------------------------------------------
// Pipelined TF32 GEMM: C[M,1024] = X[M,1024] @ W[1024,1024] + bias
// Double-buffered smem, register prefetch of next k-tile during mma,
// ONE __syncthreads per k-tile.
// ---------------------------------------------------------------------------
#define GA_STR 20
#define GB_STR 136
#define GA_TILE (128 * GA_STR)
#define GB_TILE (16 * GB_STR)

template<int MODE>
__global__ __launch_bounds__(256, 2)
void gemm_kernel(const float* __restrict__ X0, const float* __restrict__ X1,
                 const float* __restrict__ X2,
                 const float* __restrict__ W, const float* __restrict__ bias,
                 float* __restrict__ Cout)
{
    __shared__ unsigned As[2 * GA_TILE];
    __shared__ unsigned Bs[2 * GB_TILE];

    const int tid  = threadIdx.x;
    const int warp = tid >> 5, lane = tid & 31;
    const int wm = warp >> 2, wn = warp & 3;      // 2 x 4 warp grid
    const int grp = lane >> 2, qi = lane & 3;

    const int z = (MODE == 0) ? blockIdx.z : 0;
    const float* __restrict__ X =
        (MODE == 1) ? g_ctx : (z == 0 ? X0 : (z == 1 ? X1 : X2));

    const int gm0 = blockIdx.y * 128;
    const int gn0 = blockIdx.x * 128;

    // per-thread load coordinates (2 float4 each for A and B)
    const int ar0 = tid >> 2,  ak4 = tid & 3;            // A part 0
    const int ar1 = (tid + 256) >> 2, ak41 = ak4;        // A part 1 (same k4)
    const int bk0 = tid >> 5,  bn4 = tid & 31;           // B part 0
    const int bk1 = (tid + 256) >> 5;                    // B part 1 (same n4)

    const float* Ap0 = &X[(size_t)(gm0 + ar0) * DM + ak4 * 4];
    const float* Ap1 = &X[(size_t)(gm0 + ar1) * DM + ak41 * 4];
    const float* Bp0 = &W[(size_t)bk0 * DM + gn0 + bn4 * 4];
    const float* Bp1 = &W[(size_t)bk1 * DM + gn0 + bn4 * 4];

    float d[4][4][4];
#pragma unroll
    for (int mi = 0; mi < 4; mi++)
#pragma unroll
        for (int ni = 0; ni < 4; ni++)
#pragma unroll
            for (int r = 0; r < 4; r++) d[mi][ni][r] = 0.f;

    float4 a4[2], b4[2];
    // prologue: tile 0
    a4[0] = *(const float4*)(Ap0);
    a4[1] = *(const float4*)(Ap1);
    b4[0] = *(const float4*)(Bp0);
    b4[1] = *(const float4*)(Bp1);
    {
        *(uint4*)&As[ar0 * GA_STR + ak4 * 4] = cvt4(a4[0]);
        *(uint4*)&As[ar1 * GA_STR + ak4 * 4] = cvt4(a4[1]);
        *(uint4*)&Bs[bk0 * GB_STR + bn4 * 4] = cvt4(b4[0]);
        *(uint4*)&Bs[bk1 * GB_STR + bn4 * 4] = cvt4(b4[1]);
    }
    __syncthreads();

    for (int it = 0; it < 64; it++) {
        const int cur = it & 1;
        // prefetch next tile (overlaps mma below)
        if (it < 63) {
            int kn = (it + 1) * 16;
            a4[0] = *(const float4*)(Ap0 + kn);
            a4[1] = *(const float4*)(Ap1 + kn);
            b4[0] = *(const float4*)(Bp0 + (size_t)kn * DM);
            b4[1] = *(const float4*)(Bp1 + (size_t)kn * DM);
        }

        const unsigned* Ac = As + cur * GA_TILE;
        const unsigned* Bc = Bs + cur * GB_TILE;
#pragma unroll
        for (int k8 = 0; k8 < 16; k8 += 8) {
            unsigned af[4][4], bf[4][2];
#pragma unroll
            for (int mi = 0; mi < 4; mi++) {
                int row = wm * 64 + mi * 16 + grp;
                const unsigned* p = &Ac[row * GA_STR + k8 + qi];
                af[mi][0] = p[0];
                af[mi][1] = p[8 * GA_STR];
                af[mi][2] = p[4];
                af[mi][3] = p[8 * GA_STR + 4];
            }
#pragma unroll
            for (int ni = 0; ni < 4; ni++) {
                int col = wn * 32 + ni * 8 + grp;
                bf[ni][0] = Bc[(k8 + qi) * GB_STR + col];
                bf[ni][1] = Bc[(k8 + qi + 4) * GB_STR + col];
            }
#pragma unroll
            for (int mi = 0; mi < 4; mi++)
#pragma unroll
                for (int ni = 0; ni < 4; ni++)
                    mma_tf32(d[mi][ni], af[mi], bf[ni]);
        }

        if (it < 63) {
            unsigned* An = As + (cur ^ 1) * GA_TILE;
            unsigned* Bn = Bs + (cur ^ 1) * GB_TILE;
            *(uint4*)&An[ar0 * GA_STR + ak4 * 4] = cvt4(a4[0]);
            *(uint4*)&An[ar1 * GA_STR + ak4 * 4] = cvt4(a4[1]);
            *(uint4*)&Bn[bk0 * GB_STR + bn4 * 4] = cvt4(b4[0]);
            *(uint4*)&Bn[bk1 * GB_STR + bn4 * 4] = cvt4(b4[1]);
            __syncthreads();
        }
    }

#pragma unroll
    for (int ni = 0; ni < 4; ni++) {
        int gcol = gn0 + wn * 32 + ni * 8 + qi * 2;
        float b0 = bias[gcol], b1 = bias[gcol + 1];
#pragma unroll
        for (int mi = 0; mi < 4; mi++) {
            int gr = gm0 + wm * 64 + mi * 16 + grp;
#pragma unroll
            for (int half = 0; half < 2; half++) {
                int gm = gr + half * 8;
                float v0 = d[mi][ni][half * 2 + 0] + b0;
                float v1 = d[mi][ni][half * 2 + 1] + b1;
                if (MODE == 0) {
                    float* out = (z == 0) ? g_q : (z == 1) ? g_k : g_v;
                    int h = gcol >> 6, dd = gcol & 63;
                    int b = gm >> 11, s = gm & (SEQ - 1);
                    float* p = &out[(((size_t)h * BATCH + b) * SEQ + s) * DKH + dd];
                    *(float2*)p = make_float2(v0, v1);
                } else {
                    float* p = &Cout[(size_t)gm * DM + gcol];
                    *(float2*)p = make_float2(v0, v1);
                }
            }
        }
    }
}

// ---------------------------------------------------------------------------
// TF32 tensor-core flash attention per (h,b), pipelined:
//  - double-buffered K/V smem tiles, ONE __syncthreads per 64-kv iter
//  - K/V prefetch to registers overlaps the PV mma of the previous tile
//  - P (exp scores) never touches smem: accumulator->A-operand conversion is
//    done with 8 shfl.idx + 4 selects per 16x8 tile, all in registers.
// ---------------------------------------------------------------------------
#define AT_STR 68
#define KV_TILE (64 * AT_STR)
#define ATT_SMEM_BYTES ((128 + 128 + 128) * AT_STR * 4)   // Qs + 2xKs + 2xVs

__global__ __launch_bounds__(256, 2)
void attn_kernel()
{
    extern __shared__ unsigned smu[];
    unsigned* Qs = smu;                       // [128][68] tf32, pre-scaled
    unsigned* Ks = Qs + 128 * AT_STR;         // [2][64][68]
    unsigned* Vs = Ks + 2 * KV_TILE;          // [2][64][68]

    const int tid  = threadIdx.x;
    const int warp = tid >> 5, lane = tid & 31;
    const int grp  = lane >> 2, qi = lane & 3;
    const int hb   = blockIdx.y;
    const int q0   = blockIdx.x * 128;

    const float* __restrict__ Q = g_q + (size_t)hb * SEQ * DKH;
    const float* __restrict__ K = g_k + (size_t)hb * SEQ * DKH;
    const float* __restrict__ V = g_v + (size_t)hb * SEQ * DKH;

    const float inv_scale = rsqrtf((float)SEQ);

    // Stage Q (scale folded in): 128x64 = 2048 float4, 8 per thread
#pragma unroll
    for (int l = 0; l < 8; l++) {
        int idx = tid + l * 256;
        int r = idx >> 4, c4 = idx & 15;
        float4 v = *(const float4*)&Q[(size_t)(q0 + r) * DKH + c4 * 4];
        v.x *= inv_scale; v.y *= inv_scale; v.z *= inv_scale; v.w *= inv_scale;
        *(uint4*)&Qs[r * AT_STR + c4 * 4] = cvt4(v);
    }

    const int row0 = warp * 16;
    const int kvr  = tid >> 4;        // base row (0..15), rows kvr + 16*l
    const int kvc4 = tid & 15;

    float o[8][4];
    float rsum0 = 0.f, rsum1 = 0.f;
#pragma unroll
    for (int ni = 0; ni < 8; ni++)
#pragma unroll
        for (int r = 0; r < 4; r++) o[ni][r] = 0.f;

    // prologue: load + store K/V tile 0 into buffer 0
    float4 kst[4], vst[4];
#pragma unroll
    for (int l = 0; l < 4; l++) {
        int r = kvr + l * 16;
        kst[l] = *(const float4*)&K[(size_t)r * DKH + kvc4 * 4];
        vst[l] = *(const float4*)&V[(size_t)r * DKH + kvc4 * 4];
    }
#pragma unroll
    for (int l = 0; l < 4; l++) {
        int r = kvr + l * 16;
        *(uint4*)&Ks[r * AT_STR + kvc4 * 4] = cvt4(kst[l]);
        *(uint4*)&Vs[r * AT_STR + kvc4 * 4] = cvt4(vst[l]);
    }
    __syncthreads();   // Qs + tile 0 visible

    const int src1 = (lane & ~3) | (qi >> 1);
    const int src2 = src1 + 2;
    const bool oddq = (qi & 1);

    for (int it = 0; it < 32; it++) {
        const unsigned* Kc = Ks + (it & 1) * KV_TILE;
        const unsigned* Vc = Vs + (it & 1) * KV_TILE;

        // ---- S = (Q*scale) @ K^T
        float s[8][4];
#pragma unroll
        for (int ni = 0; ni < 8; ni++)
#pragma unroll
            for (int r = 0; r < 4; r++) s[ni][r] = 0.f;

#pragma unroll
        for (int k8 = 0; k8 < 64; k8 += 8) {
            unsigned a[4];
            const unsigned* ap = &Qs[(row0 + grp) * AT_STR + k8 + qi];
            a[0] = ap[0];
            a[1] = ap[8 * AT_STR];
            a[2] = ap[4];
            a[3] = ap[8 * AT_STR + 4];
#pragma unroll
            for (int ni = 0; ni < 8; ni++) {
                unsigned b[2];
                const unsigned* bp = &Kc[(ni * 8 + grp) * AT_STR + k8 + qi];
                b[0] = bp[0];
                b[1] = bp[4];
                mma_tf32(s[ni], a, b);
            }
        }

        // ---- P = exp(S) in registers (tf32 bits), rowsum partials
        unsigned ps[8][4];
#pragma unroll
        for (int ni = 0; ni < 8; ni++) {
            float e0 = __expf(s[ni][0]), e1 = __expf(s[ni][1]);
            float e2 = __expf(s[ni][2]), e3 = __expf(s[ni][3]);
            rsum0 += e0 + e1;
            rsum1 += e2 + e3;
            ps[ni][0] = to_tf32(e0); ps[ni][1] = to_tf32(e1);
            ps[ni][2] = to_tf32(e2); ps[ni][3] = to_tf32(e3);
        }

        // ---- prefetch next K/V tile (overlaps PV mma)
        if (it < 31) {
            const size_t kb = (size_t)(it + 1) * 64;
#pragma unroll
            for (int l = 0; l < 4; l++) {
                size_t r = kb + kvr + l * 16;
                kst[l] = *(const float4*)&K[r * DKH + kvc4 * 4];
                vst[l] = *(const float4*)&V[r * DKH + kvc4 * 4];
            }
        }

        // ---- O += P @ V ; A-frags built from ps via shfl (no smem)
#pragma unroll
        for (int t = 0; t < 8; t++) {
            unsigned x0 = __shfl_sync(0xffffffffu, ps[t][0], src1);
            unsigned x1 = __shfl_sync(0xffffffffu, ps[t][1], src1);
            unsigned x2 = __shfl_sync(0xffffffffu, ps[t][2], src1);
            unsigned x3 = __shfl_sync(0xffffffffu, ps[t][3], src1);
            unsigned y0 = __shfl_sync(0xffffffffu, ps[t][0], src2);
            unsigned y1 = __shfl_sync(0xffffffffu, ps[t][1], src2);
            unsigned y2 = __shfl_sync(0xffffffffu, ps[t][2], src2);
            unsigned y3 = __shfl_sync(0xffffffffu, ps[t][3], src2);
            unsigned a[4];
            a[0] = oddq ? x1 : x0;
            a[1] = oddq ? x3 : x2;
            a[2] = oddq ? y1 : y0;
            a[3] = oddq ? y3 : y2;
#pragma unroll
            for (int ni = 0; ni < 8; ni++) {
                unsigned b[2];
                const unsigned* bp = &Vc[(t * 8 + qi) * AT_STR + ni * 8 + grp];
                b[0] = bp[0];
                b[1] = bp[4 * AT_STR];
                mma_tf32(o[ni], a, b);
            }
        }

        // ---- store prefetched tile into the other buffer; one sync per iter
        if (it < 31) {
            unsigned* Kn = Ks + ((it & 1) ^ 1) * KV_TILE;
            unsigned* Vn = Vs + ((it & 1) ^ 1) * KV_TILE;
#pragma unroll
            for (int l = 0; l < 4; l++) {
                int r = kvr + l * 16;
                *(uint4*)&Kn[r * AT_STR + kvc4 * 4] = cvt4(kst[l]);
                *(uint4*)&Vn[r * AT_STR + kvc4 * 4] = cvt4(vst[l]);
            }
            __syncthreads();
        }
    }

    // Reduce rowsums across the 4 qi lanes of each quad-row
    rsum0 += __shfl_xor_sync(0xffffffffu, rsum0, 1);
    rsum0 += __shfl_xor_sync(0xffffffffu, rsum0, 2);
    rsum1 += __shfl_xor_sync(0xffffffffu, rsum1, 1);
    rsum1 += __shfl_xor_sync(0xffffffffu, rsum1, 2);
    const float rinv0 = 1.f / rsum0;
    const float rinv1 = 1.f / rsum1;

    // Write to concat layout g_ctx[(b*S+s)*1024 + h*64 + dv]
    const int h = hb >> 1, b = hb & 1;
    const int sr0 = q0 + row0 + grp;
#pragma unroll
    for (int ni = 0; ni < 8; ni++) {
        int col = h * DKH + ni * 8 + qi * 2;
        *(float2*)&g_ctx[((size_t)(b * SEQ + sr0)) * DM + col] =
            make_float2(o[ni][0] * rinv0, o[ni][1] * rinv0);
        *(float2*)&g_ctx[((size_t)(b * SEQ + sr0 + 8)) * DM + col] =
            make_float2(o[ni][2] * rinv1, o[ni][3] * rinv1);
    }
}

// ---------------------------------------------------------------------------
extern "C" void kernel_launch(void* const* d_in, const int* in_sizes, int n_in,
                              void* d_out, int out_size)
{
    (void)in_sizes; (void)n_in; (void)out_size;
    const float* query = (const float*)d_in[0];
    const float* key   = (const float*)d_in[1];
    const float* value = (const float*)d_in[2];
    const float* Wq    = (const float*)d_in[3];
    const float* bq    = (const float*)d_in[4];
    const float* Wo    = (const float*)d_in[5];
    const float* bo    = (const float*)d_in[6];
    float* out = (float*)d_out;

    cudaFuncSetAttribute(attn_kernel,
                         cudaFuncAttributeMaxDynamicSharedMemorySize,
                         ATT_SMEM_BYTES);

    dim3 blk(256);
    gemm_kernel<0><<<dim3(DM / 128, MROWS / 128, 3), blk>>>(
        query, key, value, Wq, bq, nullptr);
    attn_kernel<<<dim3(SEQ / 128, HEADS * BATCH), blk, ATT_SMEM_BYTES>>>();
    gemm_kernel<1><<<dim3(DM / 128, MROWS / 128, 1), blk>>>(
        nullptr, nullptr, nullptr, Wo, bo, out);
}

// round 5
// speedup vs baseline: 2.8705x; 1.0218x over previous
#include <cuda_runtime.h>
#include <math.h>

#define DM     1024
#define HEADS  16
#define DKH    64
#define BATCH  2
#define SEQ    2048
#define MROWS  (BATCH*SEQ)   // 4096

// Scratch (device globals: allocation-free per harness rules)
__device__ float g_q[HEADS*BATCH*SEQ*DKH];
__device__ float g_k[HEADS*BATCH*SEQ*DKH];
__device__ float g_v[HEADS*BATCH*SEQ*DKH];
__device__ float g_ctx[(size_t)MROWS*DM];

// ---- helpers --------------------------------------------------------------
__device__ __forceinline__ unsigned to_tf32(float f) {
    unsigned r;
    asm("cvt.rna.tf32.f32 %0, %1;" : "=r"(r) : "f"(f));
    return r;
}
__device__ __forceinline__ uint4 cvt4(float4 v) {
    uint4 t;
    t.x = to_tf32(v.x); t.y = to_tf32(v.y);
    t.z = to_tf32(v.z); t.w = to_tf32(v.w);
    return t;
}
__device__ __forceinline__ void mma_tf32(float d[4], const unsigned a[4],
                                         unsigned b0, unsigned b1) {
    asm("mma.sync.aligned.m16n8k8.row.col.f32.tf32.tf32.f32 "
        "{%0,%1,%2,%3}, {%4,%5,%6,%7}, {%8,%9}, {%0,%1,%2,%3};"
        : "+f"(d[0]), "+f"(d[1]), "+f"(d[2]), "+f"(d[3])
        : "r"(a[0]), "r"(a[1]), "r"(a[2]), "r"(a[3]), "r"(b0), "r"(b1));
}
// 8x8 b16 ldmatrix tile == 8x4 tf32 tile; x4 delivers a full tf32 fragment set.
__device__ __forceinline__ void ldsm_x4(unsigned r[4], unsigned saddr) {
    asm volatile("ldmatrix.sync.aligned.m8n8.x4.shared.b16 {%0,%1,%2,%3}, [%4];"
                 : "=r"(r[0]), "=r"(r[1]), "=r"(r[2]), "=r"(r[3])
                 : "r"(saddr));
}

// ---------------------------------------------------------------------------
// Pipelined TF32 GEMM: C[M,1024] = X[M,1024] @ W[1024,1024] + bias
// A fragments via ldmatrix.x4 (1 inst replaces 4 LDS.32); B scalar LDS
// (conflict-free). Double-buffered smem, one __syncthreads per k-tile.
// ---------------------------------------------------------------------------
#define GA_STR 20
#define GB_STR 136
#define GA_TILE (128 * GA_STR)
#define GB_TILE (16 * GB_STR)

template<int MODE>
__global__ __launch_bounds__(256, 2)
void gemm_kernel(const float* __restrict__ X0, const float* __restrict__ X1,
                 const float* __restrict__ X2,
                 const float* __restrict__ W, const float* __restrict__ bias,
                 float* __restrict__ Cout)
{
    __shared__ unsigned As[2 * GA_TILE];
    __shared__ unsigned Bs[2 * GB_TILE];

    const int tid  = threadIdx.x;
    const int warp = tid >> 5, lane = tid & 31;
    const int wm = warp >> 2, wn = warp & 3;      // 2 x 4 warp grid
    const int grp = lane >> 2, qi = lane & 3;

    const int z = (MODE == 0) ? blockIdx.z : 0;
    const float* __restrict__ X =
        (MODE == 1) ? g_ctx : (z == 0 ? X0 : (z == 1 ? X1 : X2));

    const int gm0 = blockIdx.y * 128;
    const int gn0 = blockIdx.x * 128;

    // ldmatrix per-lane base address into As (bytes, shared address space)
    const unsigned smA = (unsigned)__cvta_generic_to_shared(As);
    const unsigned smB = (unsigned)__cvta_generic_to_shared(Bs);
    const unsigned aLdsm = smA +
        (((wm * 64 + (lane & 7) + ((lane >> 3) & 1) * 8) * GA_STR)
         + (lane >> 4) * 4) * 4;

    // loader coordinates
    const int ar0 = tid >> 2,  ak4 = tid & 3;
    const int ar1 = (tid + 256) >> 2;
    const int bk0 = tid >> 5,  bn4 = tid & 31;
    const int bk1 = (tid + 256) >> 5;

    const float* Ap0 = &X[(size_t)(gm0 + ar0) * DM + ak4 * 4];
    const float* Ap1 = &X[(size_t)(gm0 + ar1) * DM + ak4 * 4];
    const float* Bp0 = &W[(size_t)bk0 * DM + gn0 + bn4 * 4];
    const float* Bp1 = &W[(size_t)bk1 * DM + gn0 + bn4 * 4];

    float d[4][4][4];
#pragma unroll
    for (int mi = 0; mi < 4; mi++)
#pragma unroll
        for (int ni = 0; ni < 4; ni++)
#pragma unroll
            for (int r = 0; r < 4; r++) d[mi][ni][r] = 0.f;

    float4 a4[2], b4[2];
    a4[0] = *(const float4*)(Ap0);
    a4[1] = *(const float4*)(Ap1);
    b4[0] = *(const float4*)(Bp0);
    b4[1] = *(const float4*)(Bp1);
    *(uint4*)&As[ar0 * GA_STR + ak4 * 4] = cvt4(a4[0]);
    *(uint4*)&As[ar1 * GA_STR + ak4 * 4] = cvt4(a4[1]);
    *(uint4*)&Bs[bk0 * GB_STR + bn4 * 4] = cvt4(b4[0]);
    *(uint4*)&Bs[bk1 * GB_STR + bn4 * 4] = cvt4(b4[1]);
    __syncthreads();

    for (int it = 0; it < 64; it++) {
        const int cur = it & 1;
        if (it < 63) {
            int kn = (it + 1) * 16;
            a4[0] = *(const float4*)(Ap0 + kn);
            a4[1] = *(const float4*)(Ap1 + kn);
            b4[0] = *(const float4*)(Bp0 + (size_t)kn * DM);
            b4[1] = *(const float4*)(Bp1 + (size_t)kn * DM);
        }

        const unsigned* Bc = Bs + cur * GB_TILE;
        const unsigned aOff = aLdsm + cur * (GA_TILE * 4);
#pragma unroll
        for (int k8 = 0; k8 < 16; k8 += 8) {
            unsigned af[4][4], bf[4][2];
#pragma unroll
            for (int mi = 0; mi < 4; mi++)
                ldsm_x4(af[mi], aOff + (mi * 16 * GA_STR + k8) * 4);
#pragma unroll
            for (int ni = 0; ni < 4; ni++) {
                int col = wn * 32 + ni * 8 + grp;
                bf[ni][0] = Bc[(k8 + qi) * GB_STR + col];
                bf[ni][1] = Bc[(k8 + qi + 4) * GB_STR + col];
            }
#pragma unroll
            for (int mi = 0; mi < 4; mi++)
#pragma unroll
                for (int ni = 0; ni < 4; ni++)
                    mma_tf32(d[mi][ni], af[mi], bf[ni][0], bf[ni][1]);
        }

        if (it < 63) {
            unsigned* An = As + (cur ^ 1) * GA_TILE;
            unsigned* Bn = Bs + (cur ^ 1) * GB_TILE;
            *(uint4*)&An[ar0 * GA_STR + ak4 * 4] = cvt4(a4[0]);
            *(uint4*)&An[ar1 * GA_STR + ak4 * 4] = cvt4(a4[1]);
            *(uint4*)&Bn[bk0 * GB_STR + bn4 * 4] = cvt4(b4[0]);
            *(uint4*)&Bn[bk1 * GB_STR + bn4 * 4] = cvt4(b4[1]);
            __syncthreads();
        }
    }
    (void)smB;

#pragma unroll
    for (int ni = 0; ni < 4; ni++) {
        int gcol = gn0 + wn * 32 + ni * 8 + qi * 2;
        float b0 = bias[gcol], b1 = bias[gcol + 1];
#pragma unroll
        for (int mi = 0; mi < 4; mi++) {
            int gr = gm0 + wm * 64 + mi * 16 + grp;
#pragma unroll
            for (int half = 0; half < 2; half++) {
                int gm = gr + half * 8;
                float v0 = d[mi][ni][half * 2 + 0] + b0;
                float v1 = d[mi][ni][half * 2 + 1] + b1;
                if (MODE == 0) {
                    float* out = (z == 0) ? g_q : (z == 1) ? g_k : g_v;
                    int h = gcol >> 6, dd = gcol & 63;
                    int b = gm >> 11, s = gm & (SEQ - 1);
                    float* p = &out[(((size_t)h * BATCH + b) * SEQ + s) * DKH + dd];
                    *(float2*)p = make_float2(v0, v1);
                } else {
                    float* p = &Cout[(size_t)gm * DM + gcol];
                    *(float2*)p = make_float2(v0, v1);
                }
            }
        }
    }
}

// ---------------------------------------------------------------------------
// TF32 flash attention per (h,b), fragment loads via ldmatrix:
//  Q/K fragments: LDSM.x4 from natural [row][d] layout.
//  V staged TRANSPOSED (Vt[dv][kv]) so PV B-fragments are also LDSM.x4.
//  P stays in registers (shfl-based re-fragmenting). Double-buffered K/Vt,
//  one __syncthreads per 64-kv iteration.
// ---------------------------------------------------------------------------
#define AT_STR 68
#define KV_TILE (64 * AT_STR)
#define ATT_SMEM_BYTES ((128 + 128 + 128) * AT_STR * 4)   // Qs + 2xKs + 2xVt

__global__ __launch_bounds__(256, 2)
void attn_kernel()
{
    extern __shared__ unsigned smu[];
    unsigned* Qs = smu;                       // [128][68] tf32, pre-scaled
    unsigned* Ks = Qs + 128 * AT_STR;         // [2][64][68]  K[kv][d]
    unsigned* Vt = Ks + 2 * KV_TILE;          // [2][64][68]  Vt[dv][kv]

    const int tid  = threadIdx.x;
    const int warp = tid >> 5, lane = tid & 31;
    const int grp  = lane >> 2, qi = lane & 3;
    const int hb   = blockIdx.y;
    const int q0   = blockIdx.x * 128;

    const float* __restrict__ Q = g_q + (size_t)hb * SEQ * DKH;
    const float* __restrict__ K = g_k + (size_t)hb * SEQ * DKH;
    const float* __restrict__ V = g_v + (size_t)hb * SEQ * DKH;

    const float inv_scale = rsqrtf((float)SEQ);

    // Stage Q (scale folded in)
#pragma unroll
    for (int l = 0; l < 8; l++) {
        int idx = tid + l * 256;
        int r = idx >> 4, c4 = idx & 15;
        float4 v = *(const float4*)&Q[(size_t)(q0 + r) * DKH + c4 * 4];
        v.x *= inv_scale; v.y *= inv_scale; v.z *= inv_scale; v.w *= inv_scale;
        *(uint4*)&Qs[r * AT_STR + c4 * 4] = cvt4(v);
    }

    const int row0 = warp * 16;
    const int kvr  = tid >> 4;        // 0..15 ; rows kvr + 16*l
    const int kvc4 = tid & 15;

    // ldmatrix lane bases (bytes, shared space)
    const unsigned smQ = (unsigned)__cvta_generic_to_shared(Qs);
    const unsigned smK = (unsigned)__cvta_generic_to_shared(Ks);
    const unsigned smV = (unsigned)__cvta_generic_to_shared(Vt);
    const unsigned qLdsm = smQ +
        (((row0 + (lane & 7) + ((lane >> 3) & 1) * 8) * AT_STR)
         + (lane >> 4) * 4) * 4;
    // K/Vt x4: rows = blk*8 + (lane&7), matrix index (lane>>3) -> +4 cols each
    const unsigned kvLane = (((lane & 7) * AT_STR) + (lane >> 3) * 4) * 4;

    float o[8][4];
    float rsum0 = 0.f, rsum1 = 0.f;
#pragma unroll
    for (int ni = 0; ni < 8; ni++)
#pragma unroll
        for (int r = 0; r < 4; r++) o[ni][r] = 0.f;

    // prologue: tile 0
    float4 kst[4], vst[4];
#pragma unroll
    for (int l = 0; l < 4; l++) {
        int r = kvr + l * 16;
        kst[l] = *(const float4*)&K[(size_t)r * DKH + kvc4 * 4];
        vst[l] = *(const float4*)&V[(size_t)r * DKH + kvc4 * 4];
    }
#pragma unroll
    for (int l = 0; l < 4; l++) {
        int r = kvr + l * 16;
        *(uint4*)&Ks[r * AT_STR + kvc4 * 4] = cvt4(kst[l]);
        // transpose V: Vt[dv][kv]
        Vt[(kvc4 * 4 + 0) * AT_STR + r] = to_tf32(vst[l].x);
        Vt[(kvc4 * 4 + 1) * AT_STR + r] = to_tf32(vst[l].y);
        Vt[(kvc4 * 4 + 2) * AT_STR + r] = to_tf32(vst[l].z);
        Vt[(kvc4 * 4 + 3) * AT_STR + r] = to_tf32(vst[l].w);
    }
    __syncthreads();

    const int src1 = (lane & ~3) | (qi >> 1);
    const int src2 = src1 + 2;
    const bool oddq = (qi & 1);

    for (int it = 0; it < 32; it++) {
        const unsigned curB = (unsigned)(it & 1) * (KV_TILE * 4);

        // ---- S = (Q*scale) @ K^T
        float s[8][4];
#pragma unroll
        for (int ni = 0; ni < 8; ni++)
#pragma unroll
            for (int r = 0; r < 4; r++) s[ni][r] = 0.f;

#pragma unroll
        for (int kp = 0; kp < 4; kp++) {          // k16 blocks over d
            unsigned qf0[4], qf1[4];
            ldsm_x4(qf0, qLdsm + (kp * 16) * 4);
            ldsm_x4(qf1, qLdsm + (kp * 16 + 8) * 4);
#pragma unroll
            for (int ni = 0; ni < 8; ni++) {
                unsigned kf[4];
                ldsm_x4(kf, smK + curB + kvLane
                              + (ni * 8 * AT_STR + kp * 16) * 4);
                mma_tf32(s[ni], qf0, kf[0], kf[1]);
                mma_tf32(s[ni], qf1, kf[2], kf[3]);
            }
        }

        // ---- P = exp(S) in registers, rowsum partials
        unsigned ps[8][4];
#pragma unroll
        for (int ni = 0; ni < 8; ni++) {
            float e0 = __expf(s[ni][0]), e1 = __expf(s[ni][1]);
            float e2 = __expf(s[ni][2]), e3 = __expf(s[ni][3]);
            rsum0 += e0 + e1;
            rsum1 += e2 + e3;
            ps[ni][0] = to_tf32(e0); ps[ni][1] = to_tf32(e1);
            ps[ni][2] = to_tf32(e2); ps[ni][3] = to_tf32(e3);
        }

        // ---- prefetch next K/V tile (overlaps PV mma)
        if (it < 31) {
            const size_t kb = (size_t)(it + 1) * 64;
#pragma unroll
            for (int l = 0; l < 4; l++) {
                size_t r = kb + kvr + l * 16;
                kst[l] = *(const float4*)&K[r * DKH + kvc4 * 4];
                vst[l] = *(const float4*)&V[r * DKH + kvc4 * 4];
            }
        }

        // ---- O += P @ V : A-frags from ps via shfl, B-frags LDSM from Vt
#pragma unroll
        for (int tp = 0; tp < 4; tp++) {          // kv16 blocks
            unsigned a0[4], a1[4];
            {
                const int t = 2 * tp;
                unsigned x0 = __shfl_sync(0xffffffffu, ps[t][0], src1);
                unsigned x1 = __shfl_sync(0xffffffffu, ps[t][1], src1);
                unsigned x2 = __shfl_sync(0xffffffffu, ps[t][2], src1);
                unsigned x3 = __shfl_sync(0xffffffffu, ps[t][3], src1);
                unsigned y0 = __shfl_sync(0xffffffffu, ps[t][0], src2);
                unsigned y1 = __shfl_sync(0xffffffffu, ps[t][1], src2);
                unsigned y2 = __shfl_sync(0xffffffffu, ps[t][2], src2);
                unsigned y3 = __shfl_sync(0xffffffffu, ps[t][3], src2);
                a0[0] = oddq ? x1 : x0;
                a0[1] = oddq ? x3 : x2;
                a0[2] = oddq ? y1 : y0;
                a0[3] = oddq ? y3 : y2;
            }
            {
                const int t = 2 * tp + 1;
                unsigned x0 = __shfl_sync(0xffffffffu, ps[t][0], src1);
                unsigned x1 = __shfl_sync(0xffffffffu, ps[t][1], src1);
                unsigned x2 = __shfl_sync(0xffffffffu, ps[t][2], src1);
                unsigned x3 = __shfl_sync(0xffffffffu, ps[t][3], src1);
                unsigned y0 = __shfl_sync(0xffffffffu, ps[t][0], src2);
                unsigned y1 = __shfl_sync(0xffffffffu, ps[t][1], src2);
                unsigned y2 = __shfl_sync(0xffffffffu, ps[t][2], src2);
                unsigned y3 = __shfl_sync(0xffffffffu, ps[t][3], src2);
                a1[0] = oddq ? x1 : x0;
                a1[1] = oddq ? x3 : x2;
                a1[2] = oddq ? y1 : y0;
                a1[3] = oddq ? y3 : y2;
            }
#pragma unroll
            for (int ni = 0; ni < 8; ni++) {
                unsigned vf[4];
                ldsm_x4(vf, smV + curB + kvLane
                              + (ni * 8 * AT_STR + tp * 16) * 4);
                mma_tf32(o[ni], a0, vf[0], vf[1]);
                mma_tf32(o[ni], a1, vf[2], vf[3]);
            }
        }

        // ---- store prefetched tile; one sync per iter
        if (it < 31) {
            unsigned* Kn = Ks + ((it & 1) ^ 1) * KV_TILE;
            unsigned* Vn = Vt + ((it & 1) ^ 1) * KV_TILE;
#pragma unroll
            for (int l = 0; l < 4; l++) {
                int r = kvr + l * 16;
                *(uint4*)&Kn[r * AT_STR + kvc4 * 4] = cvt4(kst[l]);
                Vn[(kvc4 * 4 + 0) * AT_STR + r] = to_tf32(vst[l].x);
                Vn[(kvc4 * 4 + 1) * AT_STR + r] = to_tf32(vst[l].y);
                Vn[(kvc4 * 4 + 2) * AT_STR + r] = to_tf32(vst[l].z);
                Vn[(kvc4 * 4 + 3) * AT_STR + r] = to_tf32(vst[l].w);
            }
            __syncthreads();
        }
    }

    // Reduce rowsums across the 4 qi lanes of each quad-row
    rsum0 += __shfl_xor_sync(0xffffffffu, rsum0, 1);
    rsum0 += __shfl_xor_sync(0xffffffffu, rsum0, 2);
    rsum1 += __shfl_xor_sync(0xffffffffu, rsum1, 1);
    rsum1 += __shfl_xor_sync(0xffffffffu, rsum1, 2);
    const float rinv0 = 1.f / rsum0;
    const float rinv1 = 1.f / rsum1;

    // Write to concat layout g_ctx[(b*S+s)*1024 + h*64 + dv]
    const int h = hb >> 1, b = hb & 1;
    const int sr0 = q0 + row0 + grp;
#pragma unroll
    for (int ni = 0; ni < 8; ni++) {
        int col = h * DKH + ni * 8 + qi * 2;
        *(float2*)&g_ctx[((size_t)(b * SEQ + sr0)) * DM + col] =
            make_float2(o[ni][0] * rinv0, o[ni][1] * rinv0);
        *(float2*)&g_ctx[((size_t)(b * SEQ + sr0 + 8)) * DM + col] =
            make_float2(o[ni][2] * rinv1, o[ni][3] * rinv1);
    }
}

// ---------------------------------------------------------------------------
extern "C" void kernel_launch(void* const* d_in, const int* in_sizes, int n_in,
                              void* d_out, int out_size)
{
    (void)in_sizes; (void)n_in; (void)out_size;
    const float* query = (const float*)d_in[0];
    const float* key   = (const float*)d_in[1];
    const float* value = (const float*)d_in[2];
    const float* Wq    = (const float*)d_in[3];
    const float* bq    = (const float*)d_in[4];
    const float* Wo    = (const float*)d_in[5];
    const float* bo    = (const float*)d_in[6];
    float* out = (float*)d_out;

    cudaFuncSetAttribute(attn_kernel,
                         cudaFuncAttributeMaxDynamicSharedMemorySize,
                         ATT_SMEM_BYTES);

    dim3 blk(256);
    gemm_kernel<0><<<dim3(DM / 128, MROWS / 128, 3), blk>>>(
        query, key, value, Wq, bq, nullptr);
    attn_kernel<<<dim3(SEQ / 128, HEADS * BATCH), blk, ATT_SMEM_BYTES>>>();
    gemm_kernel<1><<<dim3(DM / 128, MROWS / 128, 1), blk>>>(
        nullptr, nullptr, nullptr, Wo, bo, out);
}

// round 7
// speedup vs baseline: 3.3253x; 1.1584x over previous
#include <cuda_runtime.h>
#include <math.h>
#include <stdint.h>

#define DM     1024
#define HEADS  16
#define DKH    64
#define BATCH  2
#define SEQ    2048
#define MROWS  (BATCH*SEQ)   // 4096

// Scratch (device globals: allocation-free per harness rules)
__device__ float g_q[HEADS*BATCH*SEQ*DKH];
__device__ float g_k[HEADS*BATCH*SEQ*DKH];
__device__ float g_v[HEADS*BATCH*SEQ*DKH];
__device__ float g_ctx[(size_t)MROWS*DM];

// ---- helpers --------------------------------------------------------------
__device__ __forceinline__ unsigned to_tf32(float f) {
    unsigned r;
    asm("cvt.rna.tf32.f32 %0, %1;" : "=r"(r) : "f"(f));
    return r;
}
__device__ __forceinline__ uint4 cvt4(float4 v) {
    uint4 t;
    t.x = to_tf32(v.x); t.y = to_tf32(v.y);
    t.z = to_tf32(v.z); t.w = to_tf32(v.w);
    return t;
}
__device__ __forceinline__ void mma_tf32(float d[4], const unsigned a[4],
                                         unsigned b0, unsigned b1) {
    asm("mma.sync.aligned.m16n8k8.row.col.f32.tf32.tf32.f32 "
        "{%0,%1,%2,%3}, {%4,%5,%6,%7}, {%8,%9}, {%0,%1,%2,%3};"
        : "+f"(d[0]), "+f"(d[1]), "+f"(d[2]), "+f"(d[3])
        : "r"(a[0]), "r"(a[1]), "r"(a[2]), "r"(a[3]), "r"(b0), "r"(b1));
}
// 8x8 b16 ldmatrix tile == 8x4 tf32 tile; x4 delivers a full tf32 fragment set.
__device__ __forceinline__ void ldsm_x4(unsigned r[4], unsigned saddr) {
    asm volatile("ldmatrix.sync.aligned.m8n8.x4.shared.b16 {%0,%1,%2,%3}, [%4];"
                 : "=r"(r[0]), "=r"(r[1]), "=r"(r[2]), "=r"(r[3])
                 : "r"(saddr));
}

// ---------------------------------------------------------------------------
// Pipelined TF32 GEMM: C[M,1024] = X[M,1024] @ W[1024,1024] + bias
// CTA tile 128x256, 8 warps (2m x 4n), warp tile 64x64 -> 0.125 B/MAC of
// smem fragment traffic (was 0.19 at 64x32). Double-buffered dynamic smem,
// register prefetch, one __syncthreads per k16 tile.
// ---------------------------------------------------------------------------
#define GA_STR 20
#define GB_STR 264
#define GA_TILE (128 * GA_STR)
#define GB_TILE (16 * GB_STR)
#define GEMM_SMEM ((2 * GA_TILE + 2 * GB_TILE) * 4)   // 54272

template<int MODE>
__global__ __launch_bounds__(256)
void gemm_kernel(const float* __restrict__ X0, const float* __restrict__ X1,
                 const float* __restrict__ X2,
                 const float* __restrict__ W, const float* __restrict__ bias,
                 float* __restrict__ Cout)
{
    extern __shared__ unsigned smg[];
    unsigned* As = smg;                 // [2][128][20]
    unsigned* Bs = smg + 2 * GA_TILE;   // [2][16][264]

    const int tid  = threadIdx.x;
    const int warp = tid >> 5, lane = tid & 31;
    const int wm = warp >> 2, wn = warp & 3;      // 2 x 4 warp grid
    const int grp = lane >> 2, qi = lane & 3;

    const int z = (MODE == 0) ? blockIdx.z : 0;
    const float* __restrict__ X =
        (MODE == 1) ? g_ctx : (z == 0 ? X0 : (z == 1 ? X1 : X2));

    const int gm0 = blockIdx.y * 128;
    const int gn0 = blockIdx.x * 256;

    const unsigned smA = (unsigned)__cvta_generic_to_shared(As);
    const unsigned aLdsm = smA +
        (((wm * 64 + (lane & 7) + ((lane >> 3) & 1) * 8) * GA_STR)
         + (lane >> 4) * 4) * 4;

    // loader coordinates: A 512 f4 (2/thread), B 1024 f4 (4/thread)
    const int ar0 = tid >> 2, ak4 = tid & 3;
    const int bk0 = tid >> 6, bn4 = tid & 63;

    const float* Ap0 = &X[(size_t)(gm0 + ar0) * DM + ak4 * 4];
    const float* Ap1 = &X[(size_t)(gm0 + ar0 + 64) * DM + ak4 * 4];
    const float* Bp  = &W[(size_t)bk0 * DM + gn0 + bn4 * 4];

    float d[4][8][4];
#pragma unroll
    for (int mi = 0; mi < 4; mi++)
#pragma unroll
        for (int ni = 0; ni < 8; ni++)
#pragma unroll
            for (int r = 0; r < 4; r++) d[mi][ni][r] = 0.f;

    float4 a4[2], b4[4];
    a4[0] = *(const float4*)(Ap0);
    a4[1] = *(const float4*)(Ap1);
#pragma unroll
    for (int l = 0; l < 4; l++)
        b4[l] = *(const float4*)(Bp + (size_t)(4 * l) * DM);

    *(uint4*)&As[ar0 * GA_STR + ak4 * 4]        = cvt4(a4[0]);
    *(uint4*)&As[(ar0 + 64) * GA_STR + ak4 * 4] = cvt4(a4[1]);
#pragma unroll
    for (int l = 0; l < 4; l++)
        *(uint4*)&Bs[(bk0 + 4 * l) * GB_STR + bn4 * 4] = cvt4(b4[l]);
    __syncthreads();

    for (int it = 0; it < 64; it++) {
        const int cur = it & 1;
        if (it < 63) {
            int kn = (it + 1) * 16;
            a4[0] = *(const float4*)(Ap0 + kn);
            a4[1] = *(const float4*)(Ap1 + kn);
#pragma unroll
            for (int l = 0; l < 4; l++)
                b4[l] = *(const float4*)(Bp + (size_t)(kn + 4 * l) * DM);
        }

        const unsigned* Bc = Bs + cur * GB_TILE;
        const unsigned aOff = aLdsm + cur * (GA_TILE * 4);
#pragma unroll
        for (int k8 = 0; k8 < 16; k8 += 8) {
            unsigned af[4][4], bf[8][2];
#pragma unroll
            for (int mi = 0; mi < 4; mi++)
                ldsm_x4(af[mi], aOff + (mi * 16 * GA_STR + k8) * 4);
#pragma unroll
            for (int ni = 0; ni < 8; ni++) {
                int col = wn * 64 + ni * 8 + grp;
                bf[ni][0] = Bc[(k8 + qi) * GB_STR + col];
                bf[ni][1] = Bc[(k8 + qi + 4) * GB_STR + col];
            }
#pragma unroll
            for (int mi = 0; mi < 4; mi++)
#pragma unroll
                for (int ni = 0; ni < 8; ni++)
                    mma_tf32(d[mi][ni], af[mi], bf[ni][0], bf[ni][1]);
        }

        if (it < 63) {
            unsigned* An = As + (cur ^ 1) * GA_TILE;
            unsigned* Bn = Bs + (cur ^ 1) * GB_TILE;
            *(uint4*)&An[ar0 * GA_STR + ak4 * 4]        = cvt4(a4[0]);
            *(uint4*)&An[(ar0 + 64) * GA_STR + ak4 * 4] = cvt4(a4[1]);
#pragma unroll
            for (int l = 0; l < 4; l++)
                *(uint4*)&Bn[(bk0 + 4 * l) * GB_STR + bn4 * 4] = cvt4(b4[l]);
            __syncthreads();
        }
    }

#pragma unroll
    for (int ni = 0; ni < 8; ni++) {
        int gcol = gn0 + wn * 64 + ni * 8 + qi * 2;
        float b0 = bias[gcol], b1 = bias[gcol + 1];
#pragma unroll
        for (int mi = 0; mi < 4; mi++) {
            int gr = gm0 + wm * 64 + mi * 16 + grp;
#pragma unroll
            for (int half = 0; half < 2; half++) {
                int gm = gr + half * 8;
                float v0 = d[mi][ni][half * 2 + 0] + b0;
                float v1 = d[mi][ni][half * 2 + 1] + b1;
                if (MODE == 0) {
                    float* out = (z == 0) ? g_q : (z == 1) ? g_k : g_v;
                    int h = gcol >> 6, dd = gcol & 63;
                    int b = gm >> 11, s = gm & (SEQ - 1);
                    float* p = &out[(((size_t)h * BATCH + b) * SEQ + s) * DKH + dd];
                    *(float2*)p = make_float2(v0, v1);
                } else {
                    float* p = &Cout[(size_t)gm * DM + gcol];
                    *(float2*)p = make_float2(v0, v1);
                }
            }
        }
    }
}

// ---------------------------------------------------------------------------
// TF32 flash attention per (h,b): BQ=256 per CTA, 8 warps x 32 q-rows each.
// Doubled warp q-tile halves redundant K/V fragment traffic per MAC.
// Q/K frags LDSM from [row][d]; V staged transposed; P register-resident
// (shfl re-fragmenting). Double-buffered K/Vt; global loads issued at iter
// start (overlap QK), stores after QK (before PV), one sync per iter.
// ---------------------------------------------------------------------------
#define AT_STR 68
#define KV_TILE (64 * AT_STR)
#define ATT_SMEM_BYTES ((256 + 128 + 128) * AT_STR * 4)   // 139264

__global__ __launch_bounds__(256)
void attn_kernel()
{
    extern __shared__ unsigned smu[];
    unsigned* Qs = smu;                       // [256][68] tf32, pre-scaled
    unsigned* Ks = Qs + 256 * AT_STR;         // [2][64][68]  K[kv][d]
    unsigned* Vt = Ks + 2 * KV_TILE;          // [2][64][68]  Vt[dv][kv]

    const int tid  = threadIdx.x;
    const int warp = tid >> 5, lane = tid & 31;
    const int grp  = lane >> 2, qi = lane & 3;
    const int hb   = blockIdx.y;
    const int q0   = blockIdx.x * 256;

    const float* __restrict__ Q = g_q + (size_t)hb * SEQ * DKH;
    const float* __restrict__ K = g_k + (size_t)hb * SEQ * DKH;
    const float* __restrict__ V = g_v + (size_t)hb * SEQ * DKH;

    const float inv_scale = rsqrtf((float)SEQ);

    // Stage Q (scale folded in): 256x64 = 4096 f4, 16 per thread
#pragma unroll
    for (int l = 0; l < 16; l++) {
        int idx = tid + l * 256;
        int r = idx >> 4, c4 = idx & 15;
        float4 v = *(const float4*)&Q[(size_t)(q0 + r) * DKH + c4 * 4];
        v.x *= inv_scale; v.y *= inv_scale; v.z *= inv_scale; v.w *= inv_scale;
        *(uint4*)&Qs[r * AT_STR + c4 * 4] = cvt4(v);
    }

    const int row0 = warp * 32;
    const int kvr  = tid >> 4;
    const int kvc4 = tid & 15;

    const unsigned smQ = (unsigned)__cvta_generic_to_shared(Qs);
    const unsigned smK = (unsigned)__cvta_generic_to_shared(Ks);
    const unsigned smV = (unsigned)__cvta_generic_to_shared(Vt);
    const unsigned qLdsm = smQ +
        (((row0 + (lane & 7) + ((lane >> 3) & 1) * 8) * AT_STR)
         + (lane >> 4) * 4) * 4;
    const unsigned kvLane = (((lane & 7) * AT_STR) + (lane >> 3) * 4) * 4;

    float o[2][8][4];
    float rs[2][2];
#pragma unroll
    for (int m = 0; m < 2; m++) {
        rs[m][0] = 0.f; rs[m][1] = 0.f;
#pragma unroll
        for (int ni = 0; ni < 8; ni++)
#pragma unroll
            for (int r = 0; r < 4; r++) o[m][ni][r] = 0.f;
    }

    // prologue: tile 0
    {
        float4 kst[4], vst[4];
#pragma unroll
        for (int l = 0; l < 4; l++) {
            int r = kvr + l * 16;
            kst[l] = *(const float4*)&K[(size_t)r * DKH + kvc4 * 4];
            vst[l] = *(const float4*)&V[(size_t)r * DKH + kvc4 * 4];
        }
#pragma unroll
        for (int l = 0; l < 4; l++) {
            int r = kvr + l * 16;
            *(uint4*)&Ks[r * AT_STR + kvc4 * 4] = cvt4(kst[l]);
            Vt[(kvc4 * 4 + 0) * AT_STR + r] = to_tf32(vst[l].x);
            Vt[(kvc4 * 4 + 1) * AT_STR + r] = to_tf32(vst[l].y);
            Vt[(kvc4 * 4 + 2) * AT_STR + r] = to_tf32(vst[l].z);
            Vt[(kvc4 * 4 + 3) * AT_STR + r] = to_tf32(vst[l].w);
        }
    }
    __syncthreads();

    const int src1 = (lane & ~3) | (qi >> 1);
    const int src2 = src1 + 2;
    const bool oddq = (qi & 1);

    for (int it = 0; it < 32; it++) {
        const unsigned curB = (unsigned)(it & 1) * (KV_TILE * 4);

        // issue next-tile global loads first: overlap with QK mma
        float4 kst[4], vst[4];
        if (it < 31) {
            const size_t kb = (size_t)(it + 1) * 64;
#pragma unroll
            for (int l = 0; l < 4; l++) {
                size_t r = kb + kvr + l * 16;
                kst[l] = *(const float4*)&K[r * DKH + kvc4 * 4];
                vst[l] = *(const float4*)&V[r * DKH + kvc4 * 4];
            }
        }

        // ---- S = (Q*scale) @ K^T : 2 m16-tiles x 8 n8-tiles
        float s[2][8][4];
#pragma unroll
        for (int m = 0; m < 2; m++)
#pragma unroll
            for (int ni = 0; ni < 8; ni++)
#pragma unroll
                for (int r = 0; r < 4; r++) s[m][ni][r] = 0.f;

#pragma unroll
        for (int kp = 0; kp < 4; kp++) {
            unsigned qf[2][2][4];
#pragma unroll
            for (int m = 0; m < 2; m++) {
                ldsm_x4(qf[m][0], qLdsm + (m * 16 * AT_STR + kp * 16) * 4);
                ldsm_x4(qf[m][1], qLdsm + (m * 16 * AT_STR + kp * 16 + 8) * 4);
            }
#pragma unroll
            for (int ni = 0; ni < 8; ni++) {
                unsigned kf[4];
                ldsm_x4(kf, smK + curB + kvLane
                              + (ni * 8 * AT_STR + kp * 16) * 4);
#pragma unroll
                for (int m = 0; m < 2; m++) {
                    mma_tf32(s[m][ni], qf[m][0], kf[0], kf[1]);
                    mma_tf32(s[m][ni], qf[m][1], kf[2], kf[3]);
                }
            }
        }

        // ---- P = exp(S) in registers, rowsum partials
        unsigned ps[2][8][4];
#pragma unroll
        for (int m = 0; m < 2; m++)
#pragma unroll
            for (int ni = 0; ni < 8; ni++) {
                float e0 = __expf(s[m][ni][0]), e1 = __expf(s[m][ni][1]);
                float e2 = __expf(s[m][ni][2]), e3 = __expf(s[m][ni][3]);
                rs[m][0] += e0 + e1;
                rs[m][1] += e2 + e3;
                ps[m][ni][0] = to_tf32(e0); ps[m][ni][1] = to_tf32(e1);
                ps[m][ni][2] = to_tf32(e2); ps[m][ni][3] = to_tf32(e3);
            }

        // ---- store next tile into other buffer (before PV, frees regs)
        if (it < 31) {
            unsigned* Kn = Ks + ((it & 1) ^ 1) * KV_TILE;
            unsigned* Vn = Vt + ((it & 1) ^ 1) * KV_TILE;
#pragma unroll
            for (int l = 0; l < 4; l++) {
                int r = kvr + l * 16;
                *(uint4*)&Kn[r * AT_STR + kvc4 * 4] = cvt4(kst[l]);
                Vn[(kvc4 * 4 + 0) * AT_STR + r] = to_tf32(vst[l].x);
                Vn[(kvc4 * 4 + 1) * AT_STR + r] = to_tf32(vst[l].y);
                Vn[(kvc4 * 4 + 2) * AT_STR + r] = to_tf32(vst[l].z);
                Vn[(kvc4 * 4 + 3) * AT_STR + r] = to_tf32(vst[l].w);
            }
        }

        // ---- O += P @ V : A-frags from ps via shfl, B-frags LDSM from Vt
#pragma unroll
        for (int tp = 0; tp < 4; tp++) {
            unsigned a0[2][4], a1[2][4];
#pragma unroll
            for (int m = 0; m < 2; m++) {
                {
                    const unsigned* p = ps[m][2 * tp];
                    unsigned x0 = __shfl_sync(0xffffffffu, p[0], src1);
                    unsigned x1 = __shfl_sync(0xffffffffu, p[1], src1);
                    unsigned x2 = __shfl_sync(0xffffffffu, p[2], src1);
                    unsigned x3 = __shfl_sync(0xffffffffu, p[3], src1);
                    unsigned y0 = __shfl_sync(0xffffffffu, p[0], src2);
                    unsigned y1 = __shfl_sync(0xffffffffu, p[1], src2);
                    unsigned y2 = __shfl_sync(0xffffffffu, p[2], src2);
                    unsigned y3 = __shfl_sync(0xffffffffu, p[3], src2);
                    a0[m][0] = oddq ? x1 : x0;
                    a0[m][1] = oddq ? x3 : x2;
                    a0[m][2] = oddq ? y1 : y0;
                    a0[m][3] = oddq ? y3 : y2;
                }
                {
                    const unsigned* p = ps[m][2 * tp + 1];
                    unsigned x0 = __shfl_sync(0xffffffffu, p[0], src1);
                    unsigned x1 = __shfl_sync(0xffffffffu, p[1], src1);
                    unsigned x2 = __shfl_sync(0xffffffffu, p[2], src1);
                    unsigned x3 = __shfl_sync(0xffffffffu, p[3], src1);
                    unsigned y0 = __shfl_sync(0xffffffffu, p[0], src2);
                    unsigned y1 = __shfl_sync(0xffffffffu, p[1], src2);
                    unsigned y2 = __shfl_sync(0xffffffffu, p[2], src2);
                    unsigned y3 = __shfl_sync(0xffffffffu, p[3], src2);
                    a1[m][0] = oddq ? x1 : x0;
                    a1[m][1] = oddq ? x3 : x2;
                    a1[m][2] = oddq ? y1 : y0;
                    a1[m][3] = oddq ? y3 : y2;
                }
            }
#pragma unroll
            for (int ni = 0; ni < 8; ni++) {
                unsigned vf[4];
                ldsm_x4(vf, smV + curB + kvLane
                              + (ni * 8 * AT_STR + tp * 16) * 4);
#pragma unroll
                for (int m = 0; m < 2; m++) {
                    mma_tf32(o[m][ni], a0[m], vf[0], vf[1]);
                    mma_tf32(o[m][ni], a1[m], vf[2], vf[3]);
                }
            }
        }

        if (it < 31) __syncthreads();
    }

    // Reduce rowsums across the 4 qi lanes of each quad-row
#pragma unroll
    for (int m = 0; m < 2; m++)
#pragma unroll
        for (int j = 0; j < 2; j++) {
            float r = rs[m][j];
            r += __shfl_xor_sync(0xffffffffu, r, 1);
            r += __shfl_xor_sync(0xffffffffu, r, 2);
            rs[m][j] = 1.f / r;
        }

    // Write to concat layout g_ctx[(b*S+s)*1024 + h*64 + dv]
    const int h = hb >> 1, b = hb & 1;
#pragma unroll
    for (int m = 0; m < 2; m++) {
        const int sr0 = q0 + row0 + m * 16 + grp;
#pragma unroll
        for (int ni = 0; ni < 8; ni++) {
            int col = h * DKH + ni * 8 + qi * 2;
            *(float2*)&g_ctx[((size_t)(b * SEQ + sr0)) * DM + col] =
                make_float2(o[m][ni][0] * rs[m][0], o[m][ni][1] * rs[m][0]);
            *(float2*)&g_ctx[((size_t)(b * SEQ + sr0 + 8)) * DM + col] =
                make_float2(o[m][ni][2] * rs[m][1], o[m][ni][3] * rs[m][1]);
        }
    }
}

// ---------------------------------------------------------------------------
extern "C" void kernel_launch(void* const* d_in, const int* in_sizes, int n_in,
                              void* d_out, int out_size)
{
    (void)in_sizes; (void)n_in; (void)out_size;
    const float* query = (const float*)d_in[0];
    const float* key   = (const float*)d_in[1];
    const float* value = (const float*)d_in[2];
    const float* Wq    = (const float*)d_in[3];
    const float* bq    = (const float*)d_in[4];
    const float* Wo    = (const float*)d_in[5];
    const float* bo    = (const float*)d_in[6];
    float* out = (float*)d_out;

    cudaFuncSetAttribute(gemm_kernel<0>,
                         cudaFuncAttributeMaxDynamicSharedMemorySize, GEMM_SMEM);
    cudaFuncSetAttribute(gemm_kernel<1>,
                         cudaFuncAttributeMaxDynamicSharedMemorySize, GEMM_SMEM);
    cudaFuncSetAttribute(attn_kernel,
                         cudaFuncAttributeMaxDynamicSharedMemorySize,
                         ATT_SMEM_BYTES);

    dim3 blk(256);
    gemm_kernel<0><<<dim3(DM / 256, MROWS / 128, 3), blk, GEMM_SMEM>>>(
        query, key, value, Wq, bq, nullptr);
    attn_kernel<<<dim3(SEQ / 256, HEADS * BATCH), blk, ATT_SMEM_BYTES>>>();
    gemm_kernel<1><<<dim3(DM / 256, MROWS / 128, 1), blk, GEMM_SMEM>>>(
        nullptr, nullptr, nullptr, Wo, bo, out);
}

// round 8
// speedup vs baseline: 5.8919x; 1.7718x over previous
#include <cuda_runtime.h>
#include <cuda_fp16.h>
#include <math.h>
#include <stdint.h>

#define DM     1024
#define HEADS  16
#define DKH    64
#define BATCH  2
#define SEQ    2048
#define MROWS  (BATCH*SEQ)   // 4096

// Scratch (device globals; fp16 intermediates halve traffic)
__device__ __half g_q[HEADS*BATCH*SEQ*DKH];
__device__ __half g_k[HEADS*BATCH*SEQ*DKH];
__device__ __half g_v[HEADS*BATCH*SEQ*DKH];
__device__ __half g_ctx[(size_t)MROWS*DM];

// ---- helpers --------------------------------------------------------------
__device__ __forceinline__ unsigned pack_h2(float a, float b) {
    __half2 h = __floats2half2_rn(a, b);
    return *reinterpret_cast<unsigned*>(&h);
}
__device__ __forceinline__ uint2 cvt_f4h(float4 v) {
    uint2 r; r.x = pack_h2(v.x, v.y); r.y = pack_h2(v.z, v.w); return r;
}
__device__ __forceinline__ void mma_f16(float d[4], const unsigned a[4],
                                        unsigned b0, unsigned b1) {
    asm("mma.sync.aligned.m16n8k16.row.col.f32.f16.f16.f32 "
        "{%0,%1,%2,%3}, {%4,%5,%6,%7}, {%8,%9}, {%0,%1,%2,%3};"
        : "+f"(d[0]), "+f"(d[1]), "+f"(d[2]), "+f"(d[3])
        : "r"(a[0]), "r"(a[1]), "r"(a[2]), "r"(a[3]), "r"(b0), "r"(b1));
}
__device__ __forceinline__ void ldsm_x4(unsigned r[4], unsigned saddr) {
    asm volatile("ldmatrix.sync.aligned.m8n8.x4.shared.b16 {%0,%1,%2,%3}, [%4];"
                 : "=r"(r[0]), "=r"(r[1]), "=r"(r[2]), "=r"(r[3])
                 : "r"(saddr));
}
__device__ __forceinline__ void ldsm_x4t(unsigned r[4], unsigned saddr) {
    asm volatile("ldmatrix.sync.aligned.m8n8.x4.trans.shared.b16 {%0,%1,%2,%3}, [%4];"
                 : "=r"(r[0]), "=r"(r[1]), "=r"(r[2]), "=r"(r[3])
                 : "r"(saddr));
}

// ---------------------------------------------------------------------------
// fp16 tensor-core GEMM: C[M,1024] = X[M,1024] @ W[1024,1024] + bias
// CTA 128x128, 8 warps (2m x 4n), warp tile 64x32, k-stage 32, double-buffered.
// A smem [128 m][40 k-str] halfs (80B rows: ldmatrix-conflict-free),
// B smem [32 k][136 n-str] halfs (272B rows), b-frags via ldmatrix.x4.trans.
// MODE 0: X = f32 inputs (q/k/v projection); writes __half head layout,
//         with 1/sqrt(SEQ) folded into the q (z==0) output.
// MODE 1: X = g_ctx (__half); writes f32 output + bias.
// ---------------------------------------------------------------------------
#define GA_STR 40
#define GB_STR 136
#define GA_HALFS (128 * GA_STR)   // 5120
#define GB_HALFS (32 * GB_STR)    // 4352
#define GEMM_SMEM ((GA_HALFS + GB_HALFS) * 2 * 2)  // 37888 bytes

template<int MODE>
__global__ __launch_bounds__(256, 2)
void gemm_kernel(const float* __restrict__ X0, const float* __restrict__ X1,
                 const float* __restrict__ X2,
                 const float* __restrict__ W, const float* __restrict__ bias,
                 float* __restrict__ Cout)
{
    extern __shared__ __half smh[];
    __half* As = smh;                       // [2][128][40]
    __half* Bs = smh + 2 * GA_HALFS;        // [2][32][136]

    const int tid  = threadIdx.x;
    const int warp = tid >> 5, lane = tid & 31;
    const int wm = warp >> 2, wn = warp & 3;
    const int grp = lane >> 2, qi = lane & 3;

    const int z = (MODE == 0) ? blockIdx.z : 0;
    const float* __restrict__ Xf =
        (MODE == 0) ? (z == 0 ? X0 : (z == 1 ? X1 : X2)) : nullptr;

    const int gm0 = blockIdx.y * 128;
    const int gn0 = blockIdx.x * 128;

    const unsigned smA = (unsigned)__cvta_generic_to_shared(As);
    const unsigned smB = (unsigned)__cvta_generic_to_shared(Bs);
    // ldmatrix lane bases (bytes)
    const unsigned aLane = smA +
        (((wm * 64 + (lane & 7) + ((lane >> 3) & 1) * 8) * GA_STR)
         + (lane >> 4) * 8) * 2;
    const unsigned bLane = smB +
        ((((lane >> 3) * 8 + (lane & 7)) * GB_STR) + wn * 32) * 2;

    // loader coords
    const int rowA = tid >> 3, k4 = tid & 7;          // MODE0 A: f4 units
    const int rowA1 = tid >> 2, c8a = tid & 3;        // MODE1 A: uint4 units
    const int rowB = tid >> 5, n4 = tid & 31;         // B: f4 units

    float d[4][4][4];
#pragma unroll
    for (int mi = 0; mi < 4; mi++)
#pragma unroll
        for (int ni = 0; ni < 4; ni++)
#pragma unroll
            for (int r = 0; r < 4; r++) d[mi][ni][r] = 0.f;

    float4 av[4], bv[4];
    uint4  ah[2];

    // ---- prologue stage (kt = 0)
    if (MODE == 0) {
#pragma unroll
        for (int l = 0; l < 4; l++)
            av[l] = *(const float4*)&Xf[(size_t)(gm0 + rowA + l * 32) * DM + k4 * 4];
    } else {
#pragma unroll
        for (int l = 0; l < 2; l++)
            ah[l] = *(const uint4*)&g_ctx[(size_t)(gm0 + rowA1 + l * 64) * DM + c8a * 8];
    }
#pragma unroll
    for (int l = 0; l < 4; l++)
        bv[l] = *(const float4*)&W[(size_t)(rowB + l * 8) * DM + gn0 + n4 * 4];

    if (MODE == 0) {
#pragma unroll
        for (int l = 0; l < 4; l++)
            *(uint2*)&As[(rowA + l * 32) * GA_STR + k4 * 4] = cvt_f4h(av[l]);
    } else {
#pragma unroll
        for (int l = 0; l < 2; l++)
            *(uint4*)&As[(rowA1 + l * 64) * GA_STR + c8a * 8] = ah[l];
    }
#pragma unroll
    for (int l = 0; l < 4; l++)
        *(uint2*)&Bs[(rowB + l * 8) * GB_STR + n4 * 4] = cvt_f4h(bv[l]);
    __syncthreads();

    for (int it = 0; it < 32; it++) {
        const int cur = it & 1;
        // prefetch next k-tile
        if (it < 31) {
            const int kn = (it + 1) * 32;
            if (MODE == 0) {
#pragma unroll
                for (int l = 0; l < 4; l++)
                    av[l] = *(const float4*)&Xf[(size_t)(gm0 + rowA + l * 32) * DM + kn + k4 * 4];
            } else {
#pragma unroll
                for (int l = 0; l < 2; l++)
                    ah[l] = *(const uint4*)&g_ctx[(size_t)(gm0 + rowA1 + l * 64) * DM + kn + c8a * 8];
            }
#pragma unroll
            for (int l = 0; l < 4; l++)
                bv[l] = *(const float4*)&W[(size_t)(kn + rowB + l * 8) * DM + gn0 + n4 * 4];
        }

        const unsigned aB = aLane + cur * (GA_HALFS * 2);
        const unsigned bB = bLane + cur * (GB_HALFS * 2);

        unsigned bf[4][4];
#pragma unroll
        for (int ni = 0; ni < 4; ni++)
            ldsm_x4t(bf[ni], bB + ni * 16);      // k0-31 for n8-tile ni
#pragma unroll
        for (int kp = 0; kp < 2; kp++) {
            unsigned af[4][4];
#pragma unroll
            for (int mi = 0; mi < 4; mi++)
                ldsm_x4(af[mi], aB + mi * 16 * (GA_STR * 2) + kp * 32);
#pragma unroll
            for (int mi = 0; mi < 4; mi++)
#pragma unroll
                for (int ni = 0; ni < 4; ni++)
                    mma_f16(d[mi][ni], af[mi], bf[ni][kp * 2], bf[ni][kp * 2 + 1]);
        }

        if (it < 31) {
            __half* An = As + (cur ^ 1) * GA_HALFS;
            __half* Bn = Bs + (cur ^ 1) * GB_HALFS;
            if (MODE == 0) {
#pragma unroll
                for (int l = 0; l < 4; l++)
                    *(uint2*)&An[(rowA + l * 32) * GA_STR + k4 * 4] = cvt_f4h(av[l]);
            } else {
#pragma unroll
                for (int l = 0; l < 2; l++)
                    *(uint4*)&An[(rowA1 + l * 64) * GA_STR + c8a * 8] = ah[l];
            }
#pragma unroll
            for (int l = 0; l < 4; l++)
                *(uint2*)&Bn[(rowB + l * 8) * GB_STR + n4 * 4] = cvt_f4h(bv[l]);
            __syncthreads();
        }
    }

    // ---- epilogue
    const float qsc = (MODE == 0 && z == 0) ? rsqrtf((float)SEQ) : 1.0f;
#pragma unroll
    for (int ni = 0; ni < 4; ni++) {
        const int gcol = gn0 + wn * 32 + ni * 8 + qi * 2;
        const float b0 = bias[gcol], b1 = bias[gcol + 1];
#pragma unroll
        for (int mi = 0; mi < 4; mi++) {
            const int gr = gm0 + wm * 64 + mi * 16 + grp;
#pragma unroll
            for (int hh = 0; hh < 2; hh++) {
                const int gm = gr + hh * 8;
                float v0 = d[mi][ni][hh * 2 + 0] + b0;
                float v1 = d[mi][ni][hh * 2 + 1] + b1;
                if (MODE == 0) {
                    v0 *= qsc; v1 *= qsc;
                    __half* out = (z == 0) ? g_q : (z == 1) ? g_k : g_v;
                    const int h = gcol >> 6, dd = gcol & 63;
                    const int b = gm >> 11, s = gm & (SEQ - 1);
                    *(unsigned*)&out[(((size_t)h * BATCH + b) * SEQ + s) * DKH + dd]
                        = pack_h2(v0, v1);
                } else {
                    *(float2*)&Cout[(size_t)gm * DM + gcol] = make_float2(v0, v1);
                }
            }
        }
    }
}

// ---------------------------------------------------------------------------
// fp16 flash attention per (h,b): BQ=256, 8 warps x 32 q-rows.
// Q held in registers for all 32 kv-iterations (loaded once via ldmatrix).
// K b-frags: ldmatrix.x4 from [kv][d]; V b-frags: ldmatrix.x4.trans (no
// transpose staging). P->A-frag conversion is LANE-LOCAL half2 packing
// (fp16 acc layout == fp16 A-frag layout): zero shuffles, zero P smem.
// Double-buffered K/V, one __syncthreads per iteration.
// ---------------------------------------------------------------------------
#define KV_STR 72
#define KV_HALFS (64 * KV_STR)                 // 4608 halfs per tile
#define ATT_SMEM_BYTES (4 * KV_HALFS * 2)      // 36864 (Q staging aliases all)

__global__ __launch_bounds__(256)
void attn_kernel()
{
    extern __shared__ __half smh[];
    // halfs offsets: K0 = 0, K1 = 4608, V0 = 9216, V1 = 13824; Q aliases all.
    const unsigned smBase = (unsigned)__cvta_generic_to_shared(smh);

    const int tid  = threadIdx.x;
    const int warp = tid >> 5, lane = tid & 31;
    const int grp  = lane >> 2, qi = lane & 3;
    const int hb   = blockIdx.y;
    const int q0   = blockIdx.x * 256;

    const __half* __restrict__ Q = g_q + (size_t)hb * SEQ * DKH;
    const __half* __restrict__ K = g_k + (size_t)hb * SEQ * DKH;
    const __half* __restrict__ V = g_v + (size_t)hb * SEQ * DKH;

    const int row0 = warp * 32;
    const int rowL = tid >> 3, c8 = tid & 7;   // stage coords (uint4 units)

    // ---- stage Q (256 x 64 halfs) into aliased smem, then ldmatrix to regs
#pragma unroll
    for (int l = 0; l < 8; l++) {
        const int r = rowL + l * 32;
        uint4 v = *(const uint4*)&Q[(size_t)(q0 + r) * DKH + c8 * 8];
        *(uint4*)&smh[r * KV_STR + c8 * 8] = v;
    }
    __syncthreads();

    unsigned qf[2][4][4];
    {
        const unsigned qLane = smBase +
            (((row0 + (lane & 7) + ((lane >> 3) & 1) * 8) * KV_STR)
             + (lane >> 4) * 8) * 2;
#pragma unroll
        for (int m = 0; m < 2; m++)
#pragma unroll
            for (int kp = 0; kp < 4; kp++)
                ldsm_x4(qf[m][kp], qLane + m * 16 * (KV_STR * 2) + kp * 32);
    }
    __syncthreads();   // all warps done reading Q before K/V overwrite

    // ldmatrix lane bases for K (non-trans) and V (trans); rows from lane
    const unsigned kLane = smBase +
        ((((lane & 7)) * KV_STR) + (lane >> 3) * 8) * 2;   // + ni*8*stride + kq*32halfs
    const unsigned vLane = smBase + 2 * (9216) +           // V0 at half-offset 9216
        ((((lane >> 3) * 8 + (lane & 7)) * KV_STR)) * 2;   // + tq*32*stride + ni*8halfs

    float o[2][8][4];
    float rs[2][2];
#pragma unroll
    for (int m = 0; m < 2; m++) {
        rs[m][0] = 0.f; rs[m][1] = 0.f;
#pragma unroll
        for (int ni = 0; ni < 8; ni++)
#pragma unroll
            for (int r = 0; r < 4; r++) o[m][ni][r] = 0.f;
    }

    // ---- prologue: stage K/V tile 0 into buffer 0
    {
        uint4 kv0[2], vv0[2];
#pragma unroll
        for (int l = 0; l < 2; l++) {
            const int r = rowL + l * 32;
            kv0[l] = *(const uint4*)&K[(size_t)r * DKH + c8 * 8];
            vv0[l] = *(const uint4*)&V[(size_t)r * DKH + c8 * 8];
        }
#pragma unroll
        for (int l = 0; l < 2; l++) {
            const int r = rowL + l * 32;
            *(uint4*)&smh[r * KV_STR + c8 * 8] = kv0[l];              // K0
            *(uint4*)&smh[9216 + r * KV_STR + c8 * 8] = vv0[l];       // V0
        }
    }
    __syncthreads();

    for (int it = 0; it < 32; it++) {
        const unsigned curOff = (unsigned)(it & 1) * (KV_HALFS * 2);  // bytes

        // prefetch next K/V tile (overlaps QK mma)
        uint4 kst[2], vst[2];
        if (it < 31) {
            const size_t kb = (size_t)(it + 1) * 64;
#pragma unroll
            for (int l = 0; l < 2; l++) {
                const size_t r = kb + rowL + l * 32;
                kst[l] = *(const uint4*)&K[r * DKH + c8 * 8];
                vst[l] = *(const uint4*)&V[r * DKH + c8 * 8];
            }
        }

        // ---- S = Qs @ K^T
        float s[2][8][4];
#pragma unroll
        for (int m = 0; m < 2; m++)
#pragma unroll
            for (int ni = 0; ni < 8; ni++)
#pragma unroll
                for (int r = 0; r < 4; r++) s[m][ni][r] = 0.f;

#pragma unroll
        for (int kq = 0; kq < 2; kq++) {
#pragma unroll
            for (int ni = 0; ni < 8; ni++) {
                unsigned kf[4];
                ldsm_x4(kf, kLane + curOff
                             + (ni * 8 * KV_STR) * 2 + kq * 64);
#pragma unroll
                for (int m = 0; m < 2; m++) {
                    mma_f16(s[m][ni], qf[m][2 * kq],     kf[0], kf[1]);
                    mma_f16(s[m][ni], qf[m][2 * kq + 1], kf[2], kf[3]);
                }
            }
        }

        // ---- P = exp(S): lane-local half2 packs form PV A-frags directly
        unsigned ps[2][4][4];
#pragma unroll
        for (int m = 0; m < 2; m++)
#pragma unroll
            for (int tp = 0; tp < 4; tp++) {
                const float* sa = s[m][2 * tp];
                const float* sb = s[m][2 * tp + 1];
                float e0 = __expf(sa[0]), e1 = __expf(sa[1]);
                float e2 = __expf(sa[2]), e3 = __expf(sa[3]);
                float f0 = __expf(sb[0]), f1 = __expf(sb[1]);
                float f2 = __expf(sb[2]), f3 = __expf(sb[3]);
                rs[m][0] += (e0 + e1) + (f0 + f1);
                rs[m][1] += (e2 + e3) + (f2 + f3);
                ps[m][tp][0] = pack_h2(e0, e1);
                ps[m][tp][1] = pack_h2(e2, e3);
                ps[m][tp][2] = pack_h2(f0, f1);
                ps[m][tp][3] = pack_h2(f2, f3);
            }

        // ---- stage next tile into other buffer (frees prefetch regs)
        if (it < 31) {
            const unsigned nb = ((it & 1) ^ 1) * KV_HALFS;
#pragma unroll
            for (int l = 0; l < 2; l++) {
                const int r = rowL + l * 32;
                *(uint4*)&smh[nb + r * KV_STR + c8 * 8] = kst[l];
                *(uint4*)&smh[9216 + nb + r * KV_STR + c8 * 8] = vst[l];
            }
        }

        // ---- O += P @ V (V b-frags via ldmatrix.trans)
#pragma unroll
        for (int tq = 0; tq < 2; tq++) {
#pragma unroll
            for (int ni = 0; ni < 8; ni++) {
                unsigned vf[4];
                ldsm_x4t(vf, vLane + curOff
                              + (tq * 32 * KV_STR) * 2 + ni * 16);
#pragma unroll
                for (int m = 0; m < 2; m++) {
                    mma_f16(o[m][ni], ps[m][2 * tq],     vf[0], vf[1]);
                    mma_f16(o[m][ni], ps[m][2 * tq + 1], vf[2], vf[3]);
                }
            }
        }

        if (it < 31) __syncthreads();
    }

    // rowsum reduce over the 4 qi lanes
#pragma unroll
    for (int m = 0; m < 2; m++)
#pragma unroll
        for (int j = 0; j < 2; j++) {
            float r = rs[m][j];
            r += __shfl_xor_sync(0xffffffffu, r, 1);
            r += __shfl_xor_sync(0xffffffffu, r, 2);
            rs[m][j] = 1.f / r;
        }

    // write O (fp16) to concat layout g_ctx[(b*S+s)*1024 + h*64 + dv]
    const int h = hb >> 1, b = hb & 1;
#pragma unroll
    for (int m = 0; m < 2; m++) {
        const int sr0 = q0 + row0 + m * 16 + grp;
#pragma unroll
        for (int ni = 0; ni < 8; ni++) {
            const int col = h * DKH + ni * 8 + qi * 2;
            *(unsigned*)&g_ctx[((size_t)(b * SEQ + sr0)) * DM + col] =
                pack_h2(o[m][ni][0] * rs[m][0], o[m][ni][1] * rs[m][0]);
            *(unsigned*)&g_ctx[((size_t)(b * SEQ + sr0 + 8)) * DM + col] =
                pack_h2(o[m][ni][2] * rs[m][1], o[m][ni][3] * rs[m][1]);
        }
    }
}

// ---------------------------------------------------------------------------
extern "C" void kernel_launch(void* const* d_in, const int* in_sizes, int n_in,
                              void* d_out, int out_size)
{
    (void)in_sizes; (void)n_in; (void)out_size;
    const float* query = (const float*)d_in[0];
    const float* key   = (const float*)d_in[1];
    const float* value = (const float*)d_in[2];
    const float* Wq    = (const float*)d_in[3];
    const float* bq    = (const float*)d_in[4];
    const float* Wo    = (const float*)d_in[5];
    const float* bo    = (const float*)d_in[6];
    float* out = (float*)d_out;

    cudaFuncSetAttribute(gemm_kernel<0>,
                         cudaFuncAttributeMaxDynamicSharedMemorySize, GEMM_SMEM);
    cudaFuncSetAttribute(gemm_kernel<1>,
                         cudaFuncAttributeMaxDynamicSharedMemorySize, GEMM_SMEM);
    cudaFuncSetAttribute(attn_kernel,
                         cudaFuncAttributeMaxDynamicSharedMemorySize,
                         ATT_SMEM_BYTES);

    dim3 blk(256);
    gemm_kernel<0><<<dim3(DM / 128, MROWS / 128, 3), blk, GEMM_SMEM>>>(
        query, key, value, Wq, bq, nullptr);
    attn_kernel<<<dim3(SEQ / 256, HEADS * BATCH), blk, ATT_SMEM_BYTES>>>();
    gemm_kernel<1><<<dim3(DM / 128, MROWS / 128, 1), blk, GEMM_SMEM>>>(
        nullptr, nullptr, nullptr, Wo, bo, out);
}

// round 9
// speedup vs baseline: 6.6325x; 1.1257x over previous
#include <cuda_runtime.h>
#include <cuda_fp16.h>
#include <math.h>
#include <stdint.h>

#define DM     1024
#define HEADS  16
#define DKH    64
#define BATCH  2
#define SEQ    2048
#define MROWS  (BATCH*SEQ)   // 4096

// Scratch (device globals; allocation-free per harness rules)
__device__ __half g_q[HEADS*BATCH*SEQ*DKH];    // head-layout projections
__device__ __half g_k[HEADS*BATCH*SEQ*DKH];
__device__ __half g_v[HEADS*BATCH*SEQ*DKH];
__device__ __half g_ctx[(size_t)MROWS*DM];     // attention output (concat)
__device__ __half g_xq[(size_t)MROWS*DM];      // fp16 copies of inputs
__device__ __half g_xk[(size_t)MROWS*DM];
__device__ __half g_xv[(size_t)MROWS*DM];
__device__ __half g_wq[(size_t)DM*DM];         // fp16 weights
__device__ __half g_wo[(size_t)DM*DM];

// ---- helpers --------------------------------------------------------------
__device__ __forceinline__ unsigned pack_h2(float a, float b) {
    __half2 h = __floats2half2_rn(a, b);
    return *reinterpret_cast<unsigned*>(&h);
}
__device__ __forceinline__ uint2 cvt_f4h(float4 v) {
    uint2 r; r.x = pack_h2(v.x, v.y); r.y = pack_h2(v.z, v.w); return r;
}
__device__ __forceinline__ void mma_f16(float d[4], const unsigned a[4],
                                        unsigned b0, unsigned b1) {
    asm("mma.sync.aligned.m16n8k16.row.col.f32.f16.f16.f32 "
        "{%0,%1,%2,%3}, {%4,%5,%6,%7}, {%8,%9}, {%0,%1,%2,%3};"
        : "+f"(d[0]), "+f"(d[1]), "+f"(d[2]), "+f"(d[3])
        : "r"(a[0]), "r"(a[1]), "r"(a[2]), "r"(a[3]), "r"(b0), "r"(b1));
}
__device__ __forceinline__ void ldsm_x4(unsigned r[4], unsigned saddr) {
    asm volatile("ldmatrix.sync.aligned.m8n8.x4.shared.b16 {%0,%1,%2,%3}, [%4];"
                 : "=r"(r[0]), "=r"(r[1]), "=r"(r[2]), "=r"(r[3])
                 : "r"(saddr));
}
__device__ __forceinline__ void ldsm_x4t(unsigned r[4], unsigned saddr) {
    asm volatile("ldmatrix.sync.aligned.m8n8.x4.trans.shared.b16 {%0,%1,%2,%3}, [%4];"
                 : "=r"(r[0]), "=r"(r[1]), "=r"(r[2]), "=r"(r[3])
                 : "r"(saddr));
}
__device__ __forceinline__ void cp16(unsigned dst, const void* src) {
    asm volatile("cp.async.ca.shared.global [%0], [%1], 16;"
                 :: "r"(dst), "l"(src));
}
__device__ __forceinline__ void cp_commit() {
    asm volatile("cp.async.commit_group;" ::: "memory");
}
template<int N>
__device__ __forceinline__ void cp_wait() {
    asm volatile("cp.async.wait_group %0;" :: "n"(N) : "memory");
}

// ---------------------------------------------------------------------------
// f32 -> f16 conversion: z selects {query,key,value,Wq,Wo}
// ---------------------------------------------------------------------------
__global__ void cvt_kernel(const float* __restrict__ q,
                           const float* __restrict__ k,
                           const float* __restrict__ v,
                           const float* __restrict__ wq,
                           const float* __restrict__ wo)
{
    const int z = blockIdx.z;
    const float* src; __half* dst; int nf4;
    if      (z == 0) { src = q;  dst = g_xq; nf4 = MROWS * DM / 4; }
    else if (z == 1) { src = k;  dst = g_xk; nf4 = MROWS * DM / 4; }
    else if (z == 2) { src = v;  dst = g_xv; nf4 = MROWS * DM / 4; }
    else if (z == 3) { src = wq; dst = g_wq; nf4 = DM * DM / 4; }
    else             { src = wo; dst = g_wo; nf4 = DM * DM / 4; }
    for (int i = blockIdx.x * blockDim.x + threadIdx.x; i < nf4;
         i += gridDim.x * blockDim.x) {
        float4 v4 = ((const float4*)src)[i];
        ((uint2*)dst)[i] = cvt_f4h(v4);
    }
}

// ---------------------------------------------------------------------------
// fp16 GEMM, 3-stage cp.async pipeline: C[M,1024] = A @ W + bias
// CTA 128x128, 8 warps (2m x 4n), warp tile 64x32, k-stage 32.
// A smem [128][40] halfs, B smem [32][136] halfs; per-stage 18.5KB, x3.
// MODE 0: A = g_x{q,k,v} (z), B = g_wq; epilogue -> head layout (__half),
//         q output scaled by 1/sqrt(SEQ).
// MODE 1: A = g_ctx, B = g_wo; epilogue -> f32 out + bias.
// ---------------------------------------------------------------------------
#define GA_STR 40
#define GB_STR 136
#define GA_HALFS (128 * GA_STR)            // 5120
#define GB_HALFS (32 * GB_STR)             // 4352
#define G_STAGE  (GA_HALFS + GB_HALFS)     // 9472 halfs
#define GEMM_SMEM (3 * G_STAGE * 2)        // 56832 bytes

__device__ __forceinline__ void gemm_stage(const __half* __restrict__ A,
                                           const __half* __restrict__ W,
                                           unsigned smBase, int buf, int kt,
                                           int tid)
{
    const unsigned aB = smBase + (unsigned)buf * (G_STAGE * 2);
    const unsigned bB = aB + GA_HALFS * 2;
#pragma unroll
    for (int l = 0; l < 2; l++) {          // A: 512 chunks
        int c = tid + l * 256;
        int row = c >> 2, c16 = c & 3;
        cp16(aB + (row * GA_STR + c16 * 8) * 2,
             A + (size_t)row * DM + kt + c16 * 8);
    }
#pragma unroll
    for (int l = 0; l < 2; l++) {          // B: 512 chunks
        int c = tid + l * 256;
        int row = c >> 4, c16 = c & 15;
        cp16(bB + (row * GB_STR + c16 * 8) * 2,
             W + (size_t)(kt + row) * DM + c16 * 8);
    }
}

template<int MODE>
__global__ __launch_bounds__(256, 2)
void gemm_kernel(const float* __restrict__ bias, float* __restrict__ Cout)
{
    extern __shared__ __half smh[];
    const unsigned smBase = (unsigned)__cvta_generic_to_shared(smh);

    const int tid  = threadIdx.x;
    const int warp = tid >> 5, lane = tid & 31;
    const int wm = warp >> 2, wn = warp & 3;
    const int grp = lane >> 2, qi = lane & 3;

    const int z = (MODE == 0) ? blockIdx.z : 0;
    const int gm0 = blockIdx.y * 128;
    const int gn0 = blockIdx.x * 128;

    const __half* __restrict__ A =
        ((MODE == 1) ? g_ctx : (z == 0 ? g_xq : (z == 1 ? g_xk : g_xv)))
        + (size_t)gm0 * DM;
    const __half* __restrict__ W =
        ((MODE == 0) ? g_wq : g_wo) + gn0;

    // ldmatrix lane bases (byte offsets within a stage)
    const unsigned aOff =
        (((wm * 64 + (lane & 7) + ((lane >> 3) & 1) * 8) * GA_STR)
         + (lane >> 4) * 8) * 2;
    const unsigned bOff = GA_HALFS * 2 +
        ((((lane >> 3) * 8 + (lane & 7)) * GB_STR) + wn * 32) * 2;

    float d[4][4][4];
#pragma unroll
    for (int mi = 0; mi < 4; mi++)
#pragma unroll
        for (int ni = 0; ni < 4; ni++)
#pragma unroll
            for (int r = 0; r < 4; r++) d[mi][ni][r] = 0.f;

    // prologue: stages 0, 1
    gemm_stage(A, W, smBase, 0, 0, tid);  cp_commit();
    gemm_stage(A, W, smBase, 1, 32, tid); cp_commit();
    cp_wait<1>();
    __syncthreads();

    for (int it = 0; it < 32; it++) {
        const int buf = it % 3;
        if (it < 30)
            gemm_stage(A, W, smBase, (it + 2) % 3, (it + 2) * 32, tid);
        cp_commit();

        const unsigned sB = smBase + (unsigned)buf * (G_STAGE * 2);
        unsigned bf[4][4];
#pragma unroll
        for (int ni = 0; ni < 4; ni++)
            ldsm_x4t(bf[ni], sB + bOff + ni * 16);
#pragma unroll
        for (int kp = 0; kp < 2; kp++) {
            unsigned af[4][4];
#pragma unroll
            for (int mi = 0; mi < 4; mi++)
                ldsm_x4(af[mi], sB + aOff + mi * 16 * (GA_STR * 2) + kp * 32);
#pragma unroll
            for (int mi = 0; mi < 4; mi++)
#pragma unroll
                for (int ni = 0; ni < 4; ni++)
                    mma_f16(d[mi][ni], af[mi], bf[ni][kp * 2], bf[ni][kp * 2 + 1]);
        }

        cp_wait<1>();
        __syncthreads();
    }

    // ---- epilogue
    const float qsc = (MODE == 0 && z == 0) ? rsqrtf((float)SEQ) : 1.0f;
#pragma unroll
    for (int ni = 0; ni < 4; ni++) {
        const int gcol = gn0 + wn * 32 + ni * 8 + qi * 2;
        const float b0 = bias[gcol], b1 = bias[gcol + 1];
#pragma unroll
        for (int mi = 0; mi < 4; mi++) {
            const int gr = gm0 + wm * 64 + mi * 16 + grp;
#pragma unroll
            for (int hh = 0; hh < 2; hh++) {
                const int gm = gr + hh * 8;
                float v0 = d[mi][ni][hh * 2 + 0] + b0;
                float v1 = d[mi][ni][hh * 2 + 1] + b1;
                if (MODE == 0) {
                    v0 *= qsc; v1 *= qsc;
                    __half* out = (z == 0) ? g_q : (z == 1) ? g_k : g_v;
                    const int h = gcol >> 6, dd = gcol & 63;
                    const int b = gm >> 11, s = gm & (SEQ - 1);
                    *(unsigned*)&out[(((size_t)h * BATCH + b) * SEQ + s) * DKH + dd]
                        = pack_h2(v0, v1);
                } else {
                    *(float2*)&Cout[(size_t)gm * DM + gcol] = make_float2(v0, v1);
                }
            }
        }
    }
}

// ---------------------------------------------------------------------------
// fp16 flash attention per (h,b): BQ=256, 8 warps x 32 q-rows.
// Q in registers for all 32 kv-iterations; K/V streamed through a 3-stage
// cp.async pipeline. P->A-frag conversion is lane-local half2 packing.
// ---------------------------------------------------------------------------
#define KV_STR 72
#define KV_HALFS (64 * KV_STR)              // 4608 halfs (one K or V tile)
#define AT_STAGE (2 * KV_HALFS)             // 9216 halfs per stage
#define ATT_SMEM_BYTES (3 * AT_STAGE * 2)   // 55296 bytes

__device__ __forceinline__ void attn_stage(const __half* __restrict__ K,
                                           const __half* __restrict__ V,
                                           unsigned smBase, int buf,
                                           size_t kb, int tid)
{
    const unsigned base = smBase + (unsigned)buf * (AT_STAGE * 2);
#pragma unroll
    for (int l = 0; l < 2; l++) {          // K: 512 chunks
        int c = tid + l * 256;
        int row = c >> 3, c16 = c & 7;
        cp16(base + (row * KV_STR + c16 * 8) * 2,
             K + (kb + row) * DKH + c16 * 8);
    }
#pragma unroll
    for (int l = 0; l < 2; l++) {          // V: 512 chunks
        int c = tid + l * 256;
        int row = c >> 3, c16 = c & 7;
        cp16(base + KV_HALFS * 2 + (row * KV_STR + c16 * 8) * 2,
             V + (kb + row) * DKH + c16 * 8);
    }
}

__global__ __launch_bounds__(256)
void attn_kernel()
{
    extern __shared__ __half smh[];
    const unsigned smBase = (unsigned)__cvta_generic_to_shared(smh);

    const int tid  = threadIdx.x;
    const int warp = tid >> 5, lane = tid & 31;
    const int grp  = lane >> 2, qi = lane & 3;
    const int hb   = blockIdx.y;
    const int q0   = blockIdx.x * 256;

    const __half* __restrict__ Q = g_q + (size_t)hb * SEQ * DKH;
    const __half* __restrict__ K = g_k + (size_t)hb * SEQ * DKH;
    const __half* __restrict__ V = g_v + (size_t)hb * SEQ * DKH;

    const int row0 = warp * 32;
    const int rowL = tid >> 3, c8 = tid & 7;

    // ---- stage Q into (aliased) smem, ldmatrix to regs, then release smem
#pragma unroll
    for (int l = 0; l < 8; l++) {
        const int r = rowL + l * 32;
        uint4 v = *(const uint4*)&Q[(size_t)(q0 + r) * DKH + c8 * 8];
        *(uint4*)&smh[r * KV_STR + c8 * 8] = v;
    }
    __syncthreads();

    unsigned qf[2][4][4];
    {
        const unsigned qLane = smBase +
            (((row0 + (lane & 7) + ((lane >> 3) & 1) * 8) * KV_STR)
             + (lane >> 4) * 8) * 2;
#pragma unroll
        for (int m = 0; m < 2; m++)
#pragma unroll
            for (int kp = 0; kp < 4; kp++)
                ldsm_x4(qf[m][kp], qLane + m * 16 * (KV_STR * 2) + kp * 32);
    }
    __syncthreads();   // all warps done with Q before cp.async overwrites

    // ldmatrix lane bases (byte offsets within a stage)
    const unsigned kOff = (((lane & 7) * KV_STR) + (lane >> 3) * 8) * 2;
    const unsigned vOff = KV_HALFS * 2 +
        (((lane >> 3) * 8 + (lane & 7)) * KV_STR) * 2;

    float o[2][8][4];
    float rs[2][2];
#pragma unroll
    for (int m = 0; m < 2; m++) {
        rs[m][0] = 0.f; rs[m][1] = 0.f;
#pragma unroll
        for (int ni = 0; ni < 8; ni++)
#pragma unroll
            for (int r = 0; r < 4; r++) o[m][ni][r] = 0.f;
    }

    // prologue: stages 0, 1
    attn_stage(K, V, smBase, 0, 0, tid);  cp_commit();
    attn_stage(K, V, smBase, 1, 64, tid); cp_commit();
    cp_wait<1>();
    __syncthreads();

    for (int it = 0; it < 32; it++) {
        const int buf = it % 3;
        if (it < 30)
            attn_stage(K, V, smBase, (it + 2) % 3, (size_t)(it + 2) * 64, tid);
        cp_commit();

        const unsigned sB = smBase + (unsigned)buf * (AT_STAGE * 2);

        // ---- S = Q @ K^T
        float s[2][8][4];
#pragma unroll
        for (int m = 0; m < 2; m++)
#pragma unroll
            for (int ni = 0; ni < 8; ni++)
#pragma unroll
                for (int r = 0; r < 4; r++) s[m][ni][r] = 0.f;

#pragma unroll
        for (int kq = 0; kq < 2; kq++) {
#pragma unroll
            for (int ni = 0; ni < 8; ni++) {
                unsigned kf[4];
                ldsm_x4(kf, sB + kOff + (ni * 8 * KV_STR) * 2 + kq * 64);
#pragma unroll
                for (int m = 0; m < 2; m++) {
                    mma_f16(s[m][ni], qf[m][2 * kq],     kf[0], kf[1]);
                    mma_f16(s[m][ni], qf[m][2 * kq + 1], kf[2], kf[3]);
                }
            }
        }

        // ---- P = exp(S): lane-local half2 packs are the PV A-frags
        unsigned ps[2][4][4];
#pragma unroll
        for (int m = 0; m < 2; m++)
#pragma unroll
            for (int tp = 0; tp < 4; tp++) {
                const float* sa = s[m][2 * tp];
                const float* sb = s[m][2 * tp + 1];
                float e0 = __expf(sa[0]), e1 = __expf(sa[1]);
                float e2 = __expf(sa[2]), e3 = __expf(sa[3]);
                float f0 = __expf(sb[0]), f1 = __expf(sb[1]);
                float f2 = __expf(sb[2]), f3 = __expf(sb[3]);
                rs[m][0] += (e0 + e1) + (f0 + f1);
                rs[m][1] += (e2 + e3) + (f2 + f3);
                ps[m][tp][0] = pack_h2(e0, e1);
                ps[m][tp][1] = pack_h2(e2, e3);
                ps[m][tp][2] = pack_h2(f0, f1);
                ps[m][tp][3] = pack_h2(f2, f3);
            }

        // ---- O += P @ V
#pragma unroll
        for (int tq = 0; tq < 2; tq++) {
#pragma unroll
            for (int ni = 0; ni < 8; ni++) {
                unsigned vf[4];
                ldsm_x4t(vf, sB + vOff + (tq * 32 * KV_STR) * 2 + ni * 16);
#pragma unroll
                for (int m = 0; m < 2; m++) {
                    mma_f16(o[m][ni], ps[m][2 * tq],     vf[0], vf[1]);
                    mma_f16(o[m][ni], ps[m][2 * tq + 1], vf[2], vf[3]);
                }
            }
        }

        cp_wait<1>();
        __syncthreads();
    }

    // rowsum reduce over the 4 qi lanes
#pragma unroll
    for (int m = 0; m < 2; m++)
#pragma unroll
        for (int j = 0; j < 2; j++) {
            float r = rs[m][j];
            r += __shfl_xor_sync(0xffffffffu, r, 1);
            r += __shfl_xor_sync(0xffffffffu, r, 2);
            rs[m][j] = 1.f / r;
        }

    // write O (fp16) to concat layout g_ctx[(b*S+s)*1024 + h*64 + dv]
    const int h = hb >> 1, b = hb & 1;
#pragma unroll
    for (int m = 0; m < 2; m++) {
        const int sr0 = q0 + row0 + m * 16 + grp;
#pragma unroll
        for (int ni = 0; ni < 8; ni++) {
            const int col = h * DKH + ni * 8 + qi * 2;
            *(unsigned*)&g_ctx[((size_t)(b * SEQ + sr0)) * DM + col] =
                pack_h2(o[m][ni][0] * rs[m][0], o[m][ni][1] * rs[m][0]);
            *(unsigned*)&g_ctx[((size_t)(b * SEQ + sr0 + 8)) * DM + col] =
                pack_h2(o[m][ni][2] * rs[m][1], o[m][ni][3] * rs[m][1]);
        }
    }
}

// ---------------------------------------------------------------------------
extern "C" void kernel_launch(void* const* d_in, const int* in_sizes, int n_in,
                              void* d_out, int out_size)
{
    (void)in_sizes; (void)n_in; (void)out_size;
    const float* query = (const float*)d_in[0];
    const float* key   = (const float*)d_in[1];
    const float* value = (const float*)d_in[2];
    const float* bq    = (const float*)d_in[4];
    const float* Wq    = (const float*)d_in[3];
    const float* Wo    = (const float*)d_in[5];
    const float* bo    = (const float*)d_in[6];
    float* out = (float*)d_out;

    cudaFuncSetAttribute(gemm_kernel<0>,
                         cudaFuncAttributeMaxDynamicSharedMemorySize, GEMM_SMEM);
    cudaFuncSetAttribute(gemm_kernel<1>,
                         cudaFuncAttributeMaxDynamicSharedMemorySize, GEMM_SMEM);
    cudaFuncSetAttribute(attn_kernel,
                         cudaFuncAttributeMaxDynamicSharedMemorySize,
                         ATT_SMEM_BYTES);

    dim3 blk(256);
    cvt_kernel<<<dim3(1024, 1, 5), blk>>>(query, key, value, Wq, Wo);
    gemm_kernel<0><<<dim3(DM / 128, MROWS / 128, 3), blk, GEMM_SMEM>>>(bq, nullptr);
    attn_kernel<<<dim3(SEQ / 256, HEADS * BATCH), blk, ATT_SMEM_BYTES>>>();
    gemm_kernel<1><<<dim3(DM / 128, MROWS / 128, 1), blk, GEMM_SMEM>>>(bo, out);
}